// round 15
// baseline (speedup 1.0000x reference)
#include <cuda_runtime.h>
#include <cuda_fp16.h>
#include <math.h>
#include <stdint.h>

// ---------------- problem constants ----------------
#define BB   16
#define SS   128
#define TT   256
#define DD   1024
#define FIN  (DD * SS)          // 131072
#define LN_EPS 1e-5f

// ---------------- fp32 scratch (floats) ----------------
#define OFF_TMP   0L             // 3145728 (2048 x 1536)  qv2 out
#define OFF_TMP2  3145728L       // 6291456 (4096 x 1536)  kv1 out
#define OFF_V1F   9437184L       // 2097152 (16*256*512)
#define OFF_X     11534336L      // 2097152 (16*131072)
#define OFF_ATTNF 13631488L      // 524288  (16*128*256)
#define OFF_PART  14155776L      // 4194304 (256*16*1024)
#define OFF_X1    18350080L      // 16384
#define OFF_X2    18366464L      // 16384
#define FBUF_TOTAL 18382848L
__device__ __align__(128) float g_buf[FBUF_TOTAL];

// ---------------- fp16 scratch (elements) ----------------
#define BO_SGMH   0L             // 2097152
#define BO_SGML   2097152L
#define BO_VELOH  4194304L       // 4194304
#define BO_VELOL  8388608L
#define BO_QH     12582912L      // 2097152
#define BO_QL     14680064L
#define BO_KH     16777216L      // 4194304
#define BO_KL     20971520L
#define BO_WQV2H  25165824L      // 1572864 ([1536][1024])
#define BO_WQV2L  26738688L
#define BO_WKV1H  28311552L
#define BO_WKV1L  29884416L
#define BO_V1TH   31457280L      // 2097152 ([16][512][256])
#define BO_V1TL   33554432L
#define BO_ATH    35651584L      // 524288
#define BO_ATL    36175872L
#define BBUF_TOTAL 36700160L
__device__ __align__(128) __half g_hf[BBUF_TOTAL];

// ================= PTX helpers (baseline ISA, plain sm_103) =======
__device__ __forceinline__ uint32_t smem_u32(const void* p) {
    uint32_t a;
    asm("{ .reg .u64 t; cvta.to.shared.u64 t, %1; cvt.u32.u64 %0, t; }" : "=r"(a) : "l"(p));
    return a;
}
__device__ __forceinline__ void cpasync16(uint32_t dst, const void* src) {
    asm volatile("cp.async.cg.shared.global [%0], [%1], 16;" :: "r"(dst), "l"(src));
}
#define CP_COMMIT() asm volatile("cp.async.commit_group;" ::: "memory")
#define CP_WAIT(n)  asm volatile("cp.async.wait_group %0;" :: "n"(n) : "memory")

__device__ __forceinline__ void ldm_x4(uint32_t addr, uint32_t* r) {
    asm volatile("ldmatrix.sync.aligned.m8n8.x4.shared.b16 {%0,%1,%2,%3}, [%4];"
                 : "=r"(r[0]), "=r"(r[1]), "=r"(r[2]), "=r"(r[3]) : "r"(addr));
}
__device__ __forceinline__ void mma16816h(float* d, const uint32_t* a, const uint32_t* b) {
    asm volatile("mma.sync.aligned.m16n8k16.row.col.f32.f16.f16.f32 "
                 "{%0,%1,%2,%3}, {%4,%5,%6,%7}, {%8,%9}, {%0,%1,%2,%3};"
                 : "+f"(d[0]), "+f"(d[1]), "+f"(d[2]), "+f"(d[3])
                 : "r"(a[0]), "r"(a[1]), "r"(a[2]), "r"(a[3]), "r"(b[0]), "r"(b[1]));
}

// ---------------- fp16 split helpers ----------------
__device__ __forceinline__ void split2h(float a, float b, unsigned& h, unsigned& l) {
    __half2 hh = __floats2half2_rn(a, b);
    float ra = a - __half2float(__low2half(hh));
    float rb = b - __half2float(__high2half(hh));
    __half2 ll = __floats2half2_rn(ra, rb);
    h = *reinterpret_cast<unsigned*>(&hh);
    l = *reinterpret_cast<unsigned*>(&ll);
}

// ================= dense-build body (gather; zero-fill missing) =============
__device__ __forceinline__ void build_slot(int slot, const float* __restrict__ sgm,
                                           const int* __restrict__ sb, int Ns,
                                           const float* __restrict__ velo,
                                           const int* __restrict__ vb, int Nv) {
    const float* feats; const int* bidx; int N, local; long base, ldelta;
    if (slot < BB * SS) { feats = sgm; bidx = sb; N = Ns; local = SS; base = BO_SGMH; ldelta = BO_SGML - BO_SGMH; }
    else { slot -= BB * SS; feats = velo; bidx = vb; N = Nv; local = TT; base = BO_VELOH; ldelta = BO_VELOL - BO_VELOH; }
    int b = slot / local, r = slot % local;
    __shared__ int s_src;
    if (threadIdx.x == 0) {
        int lo = 0, hi = N;
        while (lo < hi) { int mid = (lo + hi) >> 1; if (bidx[mid] < b) lo = mid + 1; else hi = mid; }
        int src = lo + r;
        s_src = (src < N && bidx[src] == b) ? src : -1;
    }
    __syncthreads();
    int src = s_src;
    __half* dh = g_hf + base + (long)slot * DD;
    __half* dl = dh + ldelta;
    int c = threadIdx.x * 4;
    uint2 h = make_uint2(0, 0), l = make_uint2(0, 0);
    if (src >= 0) {
        const float4 v = *reinterpret_cast<const float4*>(feats + (long)src * DD + c);
        split2h(v.x, v.y, h.x, l.x);
        split2h(v.z, v.w, h.y, l.y);
    }
    *reinterpret_cast<uint2*>(dh + c) = h;
    *reinterpret_cast<uint2*>(dl + c) = l;
}

// ================= transpose + split hi/lo body =============================
__device__ __forceinline__ void tsp_body(float (*t)[33], const float* __restrict__ in,
                                         __half* __restrict__ oh, __half* __restrict__ ol,
                                         int R, int C, int bx, int by) {
    int r0 = by * 32, c0 = bx * 32;
    int tx = threadIdx.x & 31, ty = threadIdx.x >> 5;
#pragma unroll
    for (int i = 0; i < 32; i += 8)
        t[ty + i][tx] = in[(long)(r0 + ty + i) * C + c0 + tx];
    __syncthreads();
#pragma unroll
    for (int i = 0; i < 32; i += 8) {
        float v = t[tx][ty + i];
        __half h = __float2half_rn(v);
        __half l = __float2half_rn(v - __half2float(h));
        long o = (long)(c0 + ty + i) * R + r0 + tx;
        oh[o] = h; ol[o] = l;
    }
}

// ================= fc3a half body (1-col, LDS.128 x-tile, f32x2 FMA) ========
__device__ __forceinline__ void fc3a_half_body(float4 (*xs)[5],
                                               const float* __restrict__ W,
                                               int nchunk, int c, int half) {
    const float* x = g_buf + OFF_X;
    float* part = g_buf + OFF_PART;
    const int n = nchunk * 256 + threadIdx.x;
    const int f0 = c * 1024 + half * 512;
#pragma unroll
    for (int it = 0; it < 32; it++) {
        int i = threadIdx.x + 256 * it;
        int b = i >> 9, f = i & 511;
        float v = x[(long)b * FIN + f0 + f];
        int j = (b >> 2) ^ ((f >> 3) & 3);
        reinterpret_cast<float*>(&xs[f][j])[b & 3] = v;
    }
    __syncthreads();

    unsigned long long acc[8];
#pragma unroll
    for (int p = 0; p < 8; p++) acc[p] = 0ull;

    const float* Wp = W + (long)f0 * DD + n;
#pragma unroll 8
    for (int f = 0; f < 512; f++) {
        float w = Wp[(long)f * DD];
        unsigned long long wp;
        asm("mov.b64 %0, {%1,%1};" : "=l"(wp) : "r"(__float_as_uint(w)));
        const float4* row = xs[f];
        const int f3 = (f >> 3) & 3;
#pragma unroll
        for (int j = 0; j < 4; j++) {
            float4 v4 = row[j ^ f3];
            unsigned long long x0, x1;
            asm("mov.b64 %0, {%1,%2};" : "=l"(x0)
                : "r"(__float_as_uint(v4.x)), "r"(__float_as_uint(v4.y)));
            asm("mov.b64 %0, {%1,%2};" : "=l"(x1)
                : "r"(__float_as_uint(v4.z)), "r"(__float_as_uint(v4.w)));
            asm("fma.rn.f32x2 %0, %1, %2, %0;" : "+l"(acc[2 * j])     : "l"(x0), "l"(wp));
            asm("fma.rn.f32x2 %0, %1, %2, %0;" : "+l"(acc[2 * j + 1]) : "l"(x1), "l"(wp));
        }
    }
    const int ci = half * 128 + c;
#pragma unroll
    for (int p = 0; p < 8; p++) {
        unsigned lo, hi;
        asm("mov.b64 {%0,%1}, %2;" : "=r"(lo), "=r"(hi) : "l"(acc[p]));
        part[((long)ci * BB + 2 * p) * DD + n]     = __uint_as_float(lo);
        part[((long)ci * BB + 2 * p + 1) * DD + n] = __uint_as_float(hi);
    }
}

// ================= HMMA GEMM body (fp16 3-term, STAGES-deep pipeline) =======
template<int BM, int BN, int WM_CNT, int WN_CNT, int STAGES = 2>
__device__ __forceinline__ void gemm_body(
    const __half* __restrict__ Ah, const __half* __restrict__ Al,
    const __half* __restrict__ Bh, const __half* __restrict__ Bl,
    float* __restrict__ Cp, int K, int ldc, uint32_t sb) {
    constexpr int T   = 32 * WM_CNT * WN_CNT;
    constexpr int WTM = BM / WM_CNT, WTN = BN / WN_CNT;
    constexpr int MI  = WTM / 16;
    constexpr int NB  = WTN / 16;
    constexpr int NJ  = WTN / 8;
    constexpr int OAL = BM * 64, OBH = 2 * BM * 64, OBL = OBH + BN * 64;
    constexpr int STAGE = 2 * (BM + BN) * 64;
    constexpr int RPT = T >> 2;
    constexpr int AIT = BM / RPT, BIT = BN / RPT;

    const int tid = threadIdx.x, lane = tid & 31, wid = tid >> 5;
    const int wm = wid % WM_CNT, wn = wid / WM_CNT;
    const int r_ld = tid >> 2, c_ld = tid & 3;

    float acc[MI][NJ][4];
#pragma unroll
    for (int i = 0; i < MI; i++)
#pragma unroll
        for (int j = 0; j < NJ; j++)
#pragma unroll
            for (int q = 0; q < 4; q++) acc[i][j][q] = 0.f;

    const int NC = K >> 5;

    auto load_chunk = [&](int ci, int st) {
        const int k0 = ci << 5;
        const uint32_t s0 = sb + (uint32_t)st * STAGE;
#pragma unroll
        for (int i = 0; i < AIT; i++) {
            int r = r_ld + i * RPT;
            uint32_t d = (uint32_t)(r * 64 + ((c_ld ^ (r & 3)) << 4));
            long go = (long)r * K + k0 + c_ld * 8;
            cpasync16(s0 + d,       Ah + go);
            cpasync16(s0 + OAL + d, Al + go);
        }
#pragma unroll
        for (int i = 0; i < BIT; i++) {
            int r = r_ld + i * RPT;
            uint32_t d = (uint32_t)(r * 64 + ((c_ld ^ (r & 3)) << 4));
            long go = (long)r * K + k0 + c_ld * 8;
            cpasync16(s0 + OBH + d, Bh + go);
            cpasync16(s0 + OBL + d, Bl + go);
        }
    };

    const int a_sub = ((lane >> 3) & 1) * 8 + (lane & 7);
    const int a_kc = lane >> 4;
    const int b_sub = ((lane >> 4) & 1) * 8 + (lane & 7);
    const int b_kc = (lane >> 3) & 1;

    load_chunk(0, 0); CP_COMMIT();
    if (STAGES == 3) { load_chunk(1, 1); CP_COMMIT(); }

    for (int i = 0; i < NC; i++) {
        int st;
        if (STAGES == 2) {
            if (i + 1 < NC) { load_chunk(i + 1, (i + 1) & 1); CP_COMMIT(); CP_WAIT(1); }
            else            { CP_WAIT(0); }
            __syncthreads();
            st = i & 1;
        } else {
            if (i + 1 < NC) { CP_WAIT(1); } else { CP_WAIT(0); }
            __syncthreads();
            if (i + 2 < NC) { load_chunk(i + 2, (i + 2) % 3); CP_COMMIT(); }
            st = i % 3;
        }
        const uint32_t s0 = sb + (uint32_t)st * STAGE;
#pragma unroll
        for (int ks = 0; ks < 2; ks++) {
            uint32_t ah[MI][4], al[MI][4];
#pragma unroll
            for (int mi = 0; mi < MI; mi++) {
                int mrow = wm * WTM + mi * 16 + a_sub;
                int kc = ks * 2 + a_kc;
                uint32_t ad = s0 + mrow * 64 + ((kc ^ (mrow & 3)) << 4);
                ldm_x4(ad, ah[mi]);
                ldm_x4(ad + OAL, al[mi]);
            }
#pragma unroll
            for (int np = 0; np < NB; np++) {
                int nrow = wn * WTN + np * 16 + b_sub;
                int kc = ks * 2 + b_kc;
                uint32_t bd = s0 + OBH + nrow * 64 + ((kc ^ (nrow & 3)) << 4);
                uint32_t bh[4], bl[4];
                ldm_x4(bd, bh);
                ldm_x4(bd + BN * 64, bl);
#pragma unroll
                for (int mi = 0; mi < MI; mi++)
#pragma unroll
                    for (int j = 0; j < 2; j++) {
                        float* a4 = acc[mi][np * 2 + j];
                        mma16816h(a4, ah[mi], bh + 2 * j);
                        mma16816h(a4, ah[mi], bl + 2 * j);
                        mma16816h(a4, al[mi], bh + 2 * j);
                    }
            }
        }
        if (STAGES == 2) __syncthreads();
    }

    const int er = lane >> 2, ec = (lane & 3) * 2;
    const long mb = wm * WTM + er;
    const int nb = wn * WTN + ec;
#pragma unroll
    for (int mi = 0; mi < MI; mi++)
#pragma unroll
        for (int nj = 0; nj < NJ; nj++) {
            float* p0 = Cp + (mb + mi * 16) * ldc + nb + nj * 8;
            float* p1 = p0 + 8L * ldc;
            *reinterpret_cast<float2*>(p0) = make_float2(acc[mi][nj][0], acc[mi][nj][1]);
            *reinterpret_cast<float2*>(p1) = make_float2(acc[mi][nj][2], acc[mi][nj][3]);
        }
}

// ================= prep: build_dense (6144) + 4 weight transposes (3072) ====
__global__ void prep_kernel(const float* __restrict__ sgm, const int* __restrict__ sb, int Ns,
                            const float* __restrict__ velo, const int* __restrict__ vb, int Nv,
                            const float* __restrict__ Wq, const float* __restrict__ Wk,
                            const float* __restrict__ Wv2, const float* __restrict__ Wv1) {
    __shared__ float t[32][33];
    int bid = blockIdx.x;
    if (bid < 6144) { build_slot(bid, sgm, sb, Ns, velo, vb, Nv); return; }
    bid -= 6144;
    if (bid < 1024) {
        tsp_body(t, Wq, g_hf + BO_WQV2H, g_hf + BO_WQV2L, 1024, 1024, bid & 31, bid >> 5);
    } else if (bid < 2048) {
        bid -= 1024;
        tsp_body(t, Wk, g_hf + BO_WKV1H, g_hf + BO_WKV1L, 1024, 1024, bid & 31, bid >> 5);
    } else if (bid < 2560) {
        bid -= 2048;
        tsp_body(t, Wv2, g_hf + BO_WQV2H + 1048576L, g_hf + BO_WQV2L + 1048576L, 1024, 512,
                 bid & 15, bid >> 4);
    } else {
        bid -= 2560;
        tsp_body(t, Wv1, g_hf + BO_WKV1H + 1048576L, g_hf + BO_WKV1L + 1048576L, 1024, 512,
                 bid & 15, bid >> 4);
    }
}

// merged big GEMM: qv2 (blockIdx.y<16) + kv1 (y>=16); grid (12, 48); 3-stage
__global__ __launch_bounds__(256, 2)
void mma_gemm_big(float* __restrict__ c1, float* __restrict__ c2) {
    extern __shared__ char smem[];
    const uint32_t sb = smem_u32(smem);
    const int K = DD, ldc = 1536;
    const long n0 = (long)blockIdx.x * 128;
    const __half *Ah, *Al, *Bh, *Bl;
    float* Cp;
    if (blockIdx.y < 16) {
        long m0 = (long)blockIdx.y * 128;
        Ah = g_hf + BO_SGMH + m0 * K;  Al = g_hf + BO_SGML + m0 * K;
        Bh = g_hf + BO_WQV2H + n0 * K; Bl = g_hf + BO_WQV2L + n0 * K;
        Cp = c1 + m0 * ldc + n0;
    } else {
        long m0 = (long)(blockIdx.y - 16) * 128;
        Ah = g_hf + BO_VELOH + m0 * K; Al = g_hf + BO_VELOL + m0 * K;
        Bh = g_hf + BO_WKV1H + n0 * K; Bl = g_hf + BO_WKV1L + n0 * K;
        Cp = c2 + m0 * ldc + n0;
    }
    gemm_body<128, 128, 4, 2, 3>(Ah, Al, Bh, Bl, Cp, K, ldc, sb);
}

// ================= MEGA1: scores GEMM + v1T transpose + fc3a v2-half ========
__global__ __launch_bounds__(256)
void mega1_kernel(const float* __restrict__ W3a) {
    extern __shared__ char dsm[];
    int bid = blockIdx.x;
    if (bid < 128) {
        const uint32_t sb = smem_u32(dsm);
        int x = bid & 3, y = (bid >> 2) & 1, z = bid >> 3;
        long m0 = (long)y * 64, n0 = (long)x * 64;
        gemm_body<64, 64, 2, 4>(
            g_hf + BO_QH + (long)z * SS * DD + m0 * DD,
            g_hf + BO_QL + (long)z * SS * DD + m0 * DD,
            g_hf + BO_KH + (long)z * TT * DD + n0 * DD,
            g_hf + BO_KL + (long)z * TT * DD + n0 * DD,
            g_buf + OFF_ATTNF + (long)z * SS * TT + m0 * TT + n0, DD, TT, sb);
    } else if (bid < 2176) {
        int b2 = bid - 128;
        int bx = b2 & 15, by = (b2 >> 4) & 7, bz = b2 >> 7;
        tsp_body(reinterpret_cast<float(*)[33]>(dsm),
                 g_buf + OFF_V1F + (long)bz * TT * 512,
                 g_hf + BO_V1TH + (long)bz * 512 * TT,
                 g_hf + BO_V1TL + (long)bz * 512 * TT,
                 TT, 512, bx, by);
    } else {
        int b3 = bid - 2176;
        fc3a_half_body(reinterpret_cast<float4(*)[5]>(dsm), W3a, b3 & 3, b3 >> 2, 0);
    }
}

// ctx GEMM (batched 64x64, 8 warps)
__global__ __launch_bounds__(256, 2)
void ctx_gemm_kernel(float* __restrict__ C) {
    extern __shared__ char smem[];
    const uint32_t sb = smem_u32(smem);
    const int z = blockIdx.z;
    const long m0 = (long)blockIdx.y * 64, n0 = (long)blockIdx.x * 64;
    gemm_body<64, 64, 2, 4>(
        g_hf + BO_ATH + (long)z * SS * TT + m0 * TT,
        g_hf + BO_ATL + (long)z * SS * TT + m0 * TT,
        g_hf + BO_V1TH + (long)z * 512 * TT + n0 * TT,
        g_hf + BO_V1TL + (long)z * 512 * TT + n0 * TT,
        C + (long)z * FIN + m0 * DD + n0, TT, DD, sb);
}

// fc3a ctx-half (1-col, LDS.128): grid (4, 128)
__global__ __launch_bounds__(256)
void fc3a_ctx_kernel(const float* __restrict__ W3a) {
    __shared__ float4 xs[512][5];
    fc3a_half_body(xs, W3a, blockIdx.x, blockIdx.y, 1);
}

// ================= merged dual LayerNorm+ReLU (vectorized) ==================
__global__ void dual_ln2_kernel(const float* __restrict__ in1, const float* __restrict__ in2,
                                const float* __restrict__ gq, const float* __restrict__ bq,
                                const float* __restrict__ gv2, const float* __restrict__ bv2,
                                const float* __restrict__ gk, const float* __restrict__ bk,
                                const float* __restrict__ gv1, const float* __restrict__ bv1,
                                float* __restrict__ dX, float* __restrict__ dV1F) {
    int row = blockIdx.x, t = threadIdx.x;
    int lane = t & 31, wid = t >> 5;
    const float* ip;
    const float *g1, *b1, *g2, *b2;
    __half *oh, *ol;
    float* out2;
    if (row < 2048) {
        ip = in1 + (long)row * 1536;
        g1 = gq; b1 = bq; g2 = gv2; b2 = bv2;
        oh = g_hf + BO_QH + (long)row * 1024;
        ol = g_hf + BO_QL + (long)row * 1024;
        out2 = dX + (long)(row >> 7) * FIN + (long)(row & 127) * 1024;
    } else {
        int r2 = row - 2048;
        ip = in2 + (long)r2 * 1536;
        g1 = gk; b1 = bk; g2 = gv1; b2 = bv1;
        oh = g_hf + BO_KH + (long)r2 * 1024;
        ol = g_hf + BO_KL + (long)r2 * 1024;
        out2 = dV1F + (long)r2 * 512;
    }
    __shared__ float ws[8], wq[8];

    float4 va = *reinterpret_cast<const float4*>(ip + 4 * t);
    float s = va.x + va.y + va.z + va.w;
    float ss = va.x * va.x + va.y * va.y + va.z * va.z + va.w * va.w;
#pragma unroll
    for (int o = 16; o > 0; o >>= 1) {
        s  += __shfl_down_sync(0xffffffffu, s, o);
        ss += __shfl_down_sync(0xffffffffu, ss, o);
    }
    if (lane == 0) { ws[wid] = s; wq[wid] = ss; }
    __syncthreads();
    float st = 0.f, sq = 0.f;
#pragma unroll
    for (int i = 0; i < 8; i++) { st += ws[i]; sq += wq[i]; }
    float mean = st * (1.f / 1024.f);
    float var = sq * (1.f / 1024.f) - mean * mean;
    float r = rsqrtf(var + LN_EPS);
    {
        float4 gg = *reinterpret_cast<const float4*>(g1 + 4 * t);
        float4 bb = *reinterpret_cast<const float4*>(b1 + 4 * t);
        float v0 = fmaxf((va.x - mean) * r * gg.x + bb.x, 0.f);
        float v1 = fmaxf((va.y - mean) * r * gg.y + bb.y, 0.f);
        float v2 = fmaxf((va.z - mean) * r * gg.z + bb.z, 0.f);
        float v3 = fmaxf((va.w - mean) * r * gg.w + bb.w, 0.f);
        uint2 h, l;
        split2h(v0, v1, h.x, l.x);
        split2h(v2, v3, h.y, l.y);
        *reinterpret_cast<uint2*>(oh + 4 * t) = h;
        *reinterpret_cast<uint2*>(ol + 4 * t) = l;
    }

    float2 vb = *reinterpret_cast<const float2*>(ip + 1024 + 2 * t);
    s = vb.x + vb.y;
    ss = vb.x * vb.x + vb.y * vb.y;
#pragma unroll
    for (int o = 16; o > 0; o >>= 1) {
        s  += __shfl_down_sync(0xffffffffu, s, o);
        ss += __shfl_down_sync(0xffffffffu, ss, o);
    }
    __syncthreads();
    if (lane == 0) { ws[wid] = s; wq[wid] = ss; }
    __syncthreads();
    st = 0.f; sq = 0.f;
#pragma unroll
    for (int i = 0; i < 8; i++) { st += ws[i]; sq += wq[i]; }
    mean = st * (1.f / 512.f);
    var = sq * (1.f / 512.f) - mean * mean;
    r = rsqrtf(var + LN_EPS);
    {
        float2 gg = *reinterpret_cast<const float2*>(g2 + 2 * t);
        float2 bb = *reinterpret_cast<const float2*>(b2 + 2 * t);
        float2 o2;
        o2.x = fmaxf((vb.x - mean) * r * gg.x + bb.x, 0.f);
        o2.y = fmaxf((vb.y - mean) * r * gg.y + bb.y, 0.f);
        *reinterpret_cast<float2*>(out2 + 2 * t) = o2;
    }
}

// ================= plain LN+ReLU (fp32 out) =================
__global__ void ln_relu_kernel(const float* __restrict__ in,
                               const float* __restrict__ gamma,
                               const float* __restrict__ beta,
                               float* __restrict__ outp, int C) {
    int row = blockIdx.x;
    int t = threadIdx.x;
    const float* ip = in + (long)row * C;
    float s = 0.f, ss = 0.f;
    for (int c = t; c < C; c += 256) { float v = ip[c]; s += v; ss += v * v; }
    __shared__ float rs[256], rq[256];
    rs[t] = s; rq[t] = ss;
    __syncthreads();
    for (int o = 128; o > 0; o >>= 1) {
        if (t < o) { rs[t] += rs[t + o]; rq[t] += rq[t + o]; }
        __syncthreads();
    }
    float mean = rs[0] / C;
    float var = rq[0] / C - mean * mean;
    float r = rsqrtf(var + LN_EPS);
    float* op = outp + (long)row * C;
    for (int c = t; c < C; c += 256) {
        float v = (ip[c] - mean) * r * gamma[c] + beta[c];
        op[c] = fmaxf(v, 0.f);
    }
}

// ================= softmax (256 wide) -> packed fp16 hi/lo ================
__global__ void softmax_bf_kernel(const float* __restrict__ sc) {
    int row = blockIdx.x;
    int t = threadIdx.x;
    float v = sc[(long)row * 256 + t];
    __shared__ float red[256];
    red[t] = v;
    __syncthreads();
    for (int o = 128; o > 0; o >>= 1) { if (t < o) red[t] = fmaxf(red[t], red[t + o]); __syncthreads(); }
    float mx = red[0];
    __syncthreads();
    float e = __expf(v - mx);
    red[t] = e;
    __syncthreads();
    for (int o = 128; o > 0; o >>= 1) { if (t < o) red[t] += red[t + o]; __syncthreads(); }
    float p = e / red[0];
    float pn = __shfl_down_sync(0xffffffffu, p, 1);
    if ((t & 1) == 0) {
        unsigned h, l;
        split2h(p, pn, h, l);
        *reinterpret_cast<unsigned*>(g_hf + BO_ATH + (long)row * 256 + t) = h;
        *reinterpret_cast<unsigned*>(g_hf + BO_ATL + (long)row * 256 + t) = l;
    }
}

// fused reduce(256 chunks) + LayerNorm + ReLU -> x1; grid 16, block 1024
__global__ __launch_bounds__(1024)
void fc3a_reduce_ln_kernel(const float* __restrict__ part,
                           const float* __restrict__ gamma, const float* __restrict__ beta,
                           float* __restrict__ x1) {
    int b = blockIdx.x, n = threadIdx.x;
    float s = 0.f;
#pragma unroll 4
    for (int c = 0; c < 256; c++) s += part[((long)c * BB + b) * DD + n];
    __shared__ float rs[1024], rq[1024];
    rs[n] = s; rq[n] = s * s;
    __syncthreads();
    for (int o = 512; o > 0; o >>= 1) {
        if (n < o) { rs[n] += rs[n + o]; rq[n] += rq[n + o]; }
        __syncthreads();
    }
    float mean = rs[0] * (1.f / 1024.f);
    float var = rq[0] * (1.f / 1024.f) - mean * mean;
    float r = rsqrtf(var + LN_EPS);
    float v = (s - mean) * r * gamma[n] + beta[n];
    x1[(long)b * DD + n] = fmaxf(v, 0.f);
}

// ================= fc3b: [16,1024] @ [1024,1024] =================
__global__ void small_gemm_kernel(const float* __restrict__ A, const float* __restrict__ W,
                                  float* __restrict__ C, int K, int N) {
    int n = blockIdx.x * 256 + threadIdx.x;
    int b = blockIdx.y;
    float acc = 0.f;
#pragma unroll 4
    for (int k = 0; k < K; k++) acc += A[(long)b * K + k] * W[(long)k * N + n];
    C[(long)b * N + n] = acc;
}

// ================= heads =================
__global__ void heads_kernel(const float* __restrict__ x2,
                             const float* __restrict__ Wr, const float* __restrict__ br,
                             const float* __restrict__ Wt, const float* __restrict__ bt,
                             float* __restrict__ out) {
    int b = blockIdx.x;
    int w = threadIdx.x >> 5, lane = threadIdx.x & 31;
    __shared__ float vals[7];
    if (w < 7) {
        const float* Wp = (w < 4) ? Wr : Wt;
        int ncol = (w < 4) ? 4 : 3;
        int j = (w < 4) ? w : (w - 4);
        float acc = 0.f;
        for (int k = lane; k < DD; k += 32) acc += x2[(long)b * DD + k] * Wp[(long)k * ncol + j];
        for (int o = 16; o > 0; o >>= 1) acc += __shfl_down_sync(0xffffffffu, acc, o);
        if (lane == 0) vals[w] = acc + ((w < 4) ? br[j] : bt[j]);
    }
    __syncthreads();
    if (threadIdx.x == 0) {
        float nn = sqrtf(vals[0]*vals[0] + vals[1]*vals[1] + vals[2]*vals[2] + vals[3]*vals[3]);
        nn = fmaxf(nn, 1e-12f);
        for (int j = 0; j < 4; j++) out[b * 4 + j] = vals[j] / nn;
        for (int j = 0; j < 3; j++) out[64 + b * 3 + j] = vals[4 + j];
    }
}

// ================= host driver =================
extern "C" void kernel_launch(void* const* d_in, const int* in_sizes, int n_in,
                              void* d_out, int out_size) {
    const float* sgm_feats = nullptr; const float* velo_feats = nullptr;
    const int* sbidx = nullptr; const int* vbidx = nullptr;
    int N_sgm = 0, N_velo = 0;
    const float* w[22]; int wi = 0;
    for (int i = 0; i < n_in; i++) {
        int s = in_sizes[i];
        if (s == 3000 * 1024)      { sgm_feats = (const float*)d_in[i]; }
        else if (s == 6000 * 1024) { velo_feats = (const float*)d_in[i]; }
        else if (s == 3000)        { sbidx = (const int*)d_in[i]; N_sgm = s; }
        else if (s == 6000)        { vbidx = (const int*)d_in[i]; N_velo = s; }
        else if (wi < 22)          { w[wi++] = (const float*)d_in[i]; }
    }
    const float *gq = w[1], *bq = w[2];
    const float *Wq = w[0], *Wk = w[3], *gk = w[4], *bk = w[5];
    const float *Wv1 = w[6], *gv1 = w[7], *bv1 = w[8];
    const float *Wv2 = w[9], *gv2 = w[10], *bv2 = w[11];
    const float *W3a = w[12], *g3a = w[13], *b3a = w[14];
    const float *W3b = w[15], *g3b = w[16], *b3b = w[17];
    const float *Wr = w[18], *brr = w[19], *Wt = w[20], *btt = w[21];

    float* fb = nullptr;
    cudaGetSymbolAddress((void**)&fb, g_buf);

    float* dTMP  = fb + OFF_TMP;
    float* dTMP2 = fb + OFF_TMP2;
    float* dV1F  = fb + OFF_V1F;
    float* dX    = fb + OFF_X;
    float* dATT  = fb + OFF_ATTNF;
    float* dPART = fb + OFF_PART;
    float* dX1   = fb + OFF_X1;
    float* dX2   = fb + OFF_X2;
    float* out   = (float*)d_out;

    constexpr int SMEM_A = 3 * 2 * (128 + 128) * 64;   // 98304 (3-stage)
    constexpr int SMEM_M = 40960;                      // fc3a float4[512][5]
    cudaFuncSetAttribute(mma_gemm_big, cudaFuncAttributeMaxDynamicSharedMemorySize, SMEM_A);

    // 1. prep: dense build + all weight transposes
    prep_kernel<<<6144 + 3072, 256>>>(sgm_feats, sbidx, N_sgm, velo_feats, vbidx, N_velo,
                                      Wq, Wk, Wv2, Wv1);

    // 2. merged big GEMM: [q|v2] + [k|v1] (3-stage pipeline)
    mma_gemm_big<<<dim3(12, 48), 256, SMEM_A>>>(dTMP, dTMP2);

    // 3. merged dual-LN
    dual_ln2_kernel<<<2048 + 4096, 256>>>(dTMP, dTMP2, gq, bq, gv2, bv2,
                                          gk, bk, gv1, bv1, dX, dV1F);

    // 4. MEGA1: scores + v1T + fc3a v2-half (LDS.128, overlapped)
    mega1_kernel<<<128 + 2048 + 512, 256, SMEM_M>>>(W3a);

    // 5. softmax -> packed fp16 hi/lo
    softmax_bf_kernel<<<BB * SS, 256>>>(dATT);

    // 6. ctx = attn @ v1 -> X[:, s*1024 + 512..1023]
    ctx_gemm_kernel<<<dim3(8, 2, BB), 256, 32768>>>(dX + 512);

    // 7. fc3a ctx-half (LDS.128)
    fc3a_ctx_kernel<<<dim3(4, 128), 256>>>(W3a);

    // 8. fused reduce + LN -> x1
    fc3a_reduce_ln_kernel<<<BB, 1024>>>(dPART, g3a, b3a, dX1);

    // 9. fc3b + LN -> x2
    small_gemm_kernel<<<dim3(DD / 256, BB), 256>>>(dX1, W3b, dTMP, DD, DD);
    ln_relu_kernel<<<BB, 256>>>(dTMP, g3b, b3b, dX2, DD);

    // 10. heads
    heads_kernel<<<BB, 256>>>(dX2, Wr, brr, Wt, btt, out);
    (void)out_size;
}

// round 16
// speedup vs baseline: 1.0816x; 1.0816x over previous
#include <cuda_runtime.h>
#include <cuda_fp16.h>
#include <math.h>
#include <stdint.h>

// ---------------- problem constants ----------------
#define BB   16
#define SS   128
#define TT   256
#define DD   1024
#define FIN  (DD * SS)          // 131072
#define LN_EPS 1e-5f

// ---------------- fp32 scratch (floats) ----------------
#define OFF_TMP   0L             // 3145728 (2048 x 1536)  qv2 out
#define OFF_TMP2  3145728L       // 6291456 (4096 x 1536)  kv1 out
#define OFF_V1F   9437184L       // 2097152 (16*256*512)
#define OFF_X     11534336L      // 2097152 (16*131072)
#define OFF_ATTNF 13631488L      // 524288  (16*128*256)
#define OFF_PART  14155776L      // 4194304 (256*16*1024)
#define OFF_X1    18350080L      // 16384
#define OFF_X2    18366464L      // 16384
#define FBUF_TOTAL 18382848L
__device__ __align__(128) float g_buf[FBUF_TOTAL];

// ---------------- fp16 scratch (elements) ----------------
#define BO_SGMH   0L             // 2097152
#define BO_SGML   2097152L
#define BO_VELOH  4194304L       // 4194304
#define BO_VELOL  8388608L
#define BO_QH     12582912L      // 2097152
#define BO_QL     14680064L
#define BO_KH     16777216L      // 4194304
#define BO_KL     20971520L
#define BO_WQV2H  25165824L      // 1572864 ([1536][1024], single fp16)
#define BO_WKV1H  28311552L      // single fp16
#define BO_V1TH   31457280L      // 2097152 ([16][512][256])
#define BO_V1TL   33554432L
#define BO_ATH    35651584L      // 524288
#define BO_ATL    36175872L
#define BBUF_TOTAL 36700160L
__device__ __align__(128) __half g_hf[BBUF_TOTAL];

// ================= PTX helpers (baseline ISA, plain sm_103) =======
__device__ __forceinline__ uint32_t smem_u32(const void* p) {
    uint32_t a;
    asm("{ .reg .u64 t; cvta.to.shared.u64 t, %1; cvt.u32.u64 %0, t; }" : "=r"(a) : "l"(p));
    return a;
}
__device__ __forceinline__ void cpasync16(uint32_t dst, const void* src) {
    asm volatile("cp.async.cg.shared.global [%0], [%1], 16;" :: "r"(dst), "l"(src));
}
#define CP_COMMIT() asm volatile("cp.async.commit_group;" ::: "memory")
#define CP_WAIT(n)  asm volatile("cp.async.wait_group %0;" :: "n"(n) : "memory")

__device__ __forceinline__ void ldm_x4(uint32_t addr, uint32_t* r) {
    asm volatile("ldmatrix.sync.aligned.m8n8.x4.shared.b16 {%0,%1,%2,%3}, [%4];"
                 : "=r"(r[0]), "=r"(r[1]), "=r"(r[2]), "=r"(r[3]) : "r"(addr));
}
__device__ __forceinline__ void mma16816h(float* d, const uint32_t* a, const uint32_t* b) {
    asm volatile("mma.sync.aligned.m16n8k16.row.col.f32.f16.f16.f32 "
                 "{%0,%1,%2,%3}, {%4,%5,%6,%7}, {%8,%9}, {%0,%1,%2,%3};"
                 : "+f"(d[0]), "+f"(d[1]), "+f"(d[2]), "+f"(d[3])
                 : "r"(a[0]), "r"(a[1]), "r"(a[2]), "r"(a[3]), "r"(b[0]), "r"(b[1]));
}

// ---------------- fp16 split helpers ----------------
__device__ __forceinline__ void split2h(float a, float b, unsigned& h, unsigned& l) {
    __half2 hh = __floats2half2_rn(a, b);
    float ra = a - __half2float(__low2half(hh));
    float rb = b - __half2float(__high2half(hh));
    __half2 ll = __floats2half2_rn(ra, rb);
    h = *reinterpret_cast<unsigned*>(&hh);
    l = *reinterpret_cast<unsigned*>(&ll);
}

// ================= dense-build body (gather; zero-fill missing) =============
__device__ __forceinline__ void build_slot(int slot, const float* __restrict__ sgm,
                                           const int* __restrict__ sb, int Ns,
                                           const float* __restrict__ velo,
                                           const int* __restrict__ vb, int Nv) {
    const float* feats; const int* bidx; int N, local; long base, ldelta;
    if (slot < BB * SS) { feats = sgm; bidx = sb; N = Ns; local = SS; base = BO_SGMH; ldelta = BO_SGML - BO_SGMH; }
    else { slot -= BB * SS; feats = velo; bidx = vb; N = Nv; local = TT; base = BO_VELOH; ldelta = BO_VELOL - BO_VELOH; }
    int b = slot / local, r = slot % local;
    __shared__ int s_src;
    if (threadIdx.x == 0) {
        int lo = 0, hi = N;
        while (lo < hi) { int mid = (lo + hi) >> 1; if (bidx[mid] < b) lo = mid + 1; else hi = mid; }
        int src = lo + r;
        s_src = (src < N && bidx[src] == b) ? src : -1;
    }
    __syncthreads();
    int src = s_src;
    __half* dh = g_hf + base + (long)slot * DD;
    __half* dl = dh + ldelta;
    int c = threadIdx.x * 4;
    uint2 h = make_uint2(0, 0), l = make_uint2(0, 0);
    if (src >= 0) {
        const float4 v = *reinterpret_cast<const float4*>(feats + (long)src * DD + c);
        split2h(v.x, v.y, h.x, l.x);
        split2h(v.z, v.w, h.y, l.y);
    }
    *reinterpret_cast<uint2*>(dh + c) = h;
    *reinterpret_cast<uint2*>(dl + c) = l;
}

// ================= transpose bodies =========================================
__device__ __forceinline__ void tsp_body(float (*t)[33], const float* __restrict__ in,
                                         __half* __restrict__ oh, __half* __restrict__ ol,
                                         int R, int C, int bx, int by) {
    int r0 = by * 32, c0 = bx * 32;
    int tx = threadIdx.x & 31, ty = threadIdx.x >> 5;
#pragma unroll
    for (int i = 0; i < 32; i += 8)
        t[ty + i][tx] = in[(long)(r0 + ty + i) * C + c0 + tx];
    __syncthreads();
#pragma unroll
    for (int i = 0; i < 32; i += 8) {
        float v = t[tx][ty + i];
        __half h = __float2half_rn(v);
        __half l = __float2half_rn(v - __half2float(h));
        long o = (long)(c0 + ty + i) * R + r0 + tx;
        oh[o] = h; ol[o] = l;
    }
}
// single fp16 output (weights)
__device__ __forceinline__ void tsp_body1(float (*t)[33], const float* __restrict__ in,
                                          __half* __restrict__ oh,
                                          int R, int C, int bx, int by) {
    int r0 = by * 32, c0 = bx * 32;
    int tx = threadIdx.x & 31, ty = threadIdx.x >> 5;
#pragma unroll
    for (int i = 0; i < 32; i += 8)
        t[ty + i][tx] = in[(long)(r0 + ty + i) * C + c0 + tx];
    __syncthreads();
#pragma unroll
    for (int i = 0; i < 32; i += 8) {
        float v = t[tx][ty + i];
        oh[(long)(c0 + ty + i) * R + r0 + tx] = __float2half_rn(v);
    }
}

// ================= fc3a half body (1-col, LDS.128 x-tile, f32x2 FMA) ========
__device__ __forceinline__ void fc3a_half_body(float4 (*xs)[5],
                                               const float* __restrict__ W,
                                               int nchunk, int c, int half) {
    const float* x = g_buf + OFF_X;
    float* part = g_buf + OFF_PART;
    const int n = nchunk * 256 + threadIdx.x;
    const int f0 = c * 1024 + half * 512;
#pragma unroll
    for (int it = 0; it < 32; it++) {
        int i = threadIdx.x + 256 * it;
        int b = i >> 9, f = i & 511;
        float v = x[(long)b * FIN + f0 + f];
        int j = (b >> 2) ^ ((f >> 3) & 3);
        reinterpret_cast<float*>(&xs[f][j])[b & 3] = v;
    }
    __syncthreads();

    unsigned long long acc[8];
#pragma unroll
    for (int p = 0; p < 8; p++) acc[p] = 0ull;

    const float* Wp = W + (long)f0 * DD + n;
#pragma unroll 8
    for (int f = 0; f < 512; f++) {
        float w = Wp[(long)f * DD];
        unsigned long long wp;
        asm("mov.b64 %0, {%1,%1};" : "=l"(wp) : "r"(__float_as_uint(w)));
        const float4* row = xs[f];
        const int f3 = (f >> 3) & 3;
#pragma unroll
        for (int j = 0; j < 4; j++) {
            float4 v4 = row[j ^ f3];
            unsigned long long x0, x1;
            asm("mov.b64 %0, {%1,%2};" : "=l"(x0)
                : "r"(__float_as_uint(v4.x)), "r"(__float_as_uint(v4.y)));
            asm("mov.b64 %0, {%1,%2};" : "=l"(x1)
                : "r"(__float_as_uint(v4.z)), "r"(__float_as_uint(v4.w)));
            asm("fma.rn.f32x2 %0, %1, %2, %0;" : "+l"(acc[2 * j])     : "l"(x0), "l"(wp));
            asm("fma.rn.f32x2 %0, %1, %2, %0;" : "+l"(acc[2 * j + 1]) : "l"(x1), "l"(wp));
        }
    }
    const int ci = half * 128 + c;
#pragma unroll
    for (int p = 0; p < 8; p++) {
        unsigned lo, hi;
        asm("mov.b64 {%0,%1}, %2;" : "=r"(lo), "=r"(hi) : "l"(acc[p]));
        part[((long)ci * BB + 2 * p) * DD + n]     = __uint_as_float(lo);
        part[((long)ci * BB + 2 * p + 1) * DD + n] = __uint_as_float(hi);
    }
}

// ================= HMMA GEMM body (fp16; BSING: B single, 2 terms) ==========
template<int BM, int BN, int WM_CNT, int WN_CNT, bool BSING = false>
__device__ __forceinline__ void gemm_body(
    const __half* __restrict__ Ah, const __half* __restrict__ Al,
    const __half* __restrict__ Bh, const __half* __restrict__ Bl,
    float* __restrict__ Cp, int K, int ldc, uint32_t sb) {
    constexpr int T   = 32 * WM_CNT * WN_CNT;
    constexpr int WTM = BM / WM_CNT, WTN = BN / WN_CNT;
    constexpr int MI  = WTM / 16;
    constexpr int NB  = WTN / 16;
    constexpr int NJ  = WTN / 8;
    constexpr int OAL = BM * 64, OBH = 2 * BM * 64, OBL = OBH + BN * 64;
    constexpr int STAGE = (2 * BM + (BSING ? BN : 2 * BN)) * 64;
    constexpr int RPT = T >> 2;
    constexpr int AIT = BM / RPT, BIT = BN / RPT;

    const int tid = threadIdx.x, lane = tid & 31, wid = tid >> 5;
    const int wm = wid % WM_CNT, wn = wid / WM_CNT;
    const int r_ld = tid >> 2, c_ld = tid & 3;

    float acc[MI][NJ][4];
#pragma unroll
    for (int i = 0; i < MI; i++)
#pragma unroll
        for (int j = 0; j < NJ; j++)
#pragma unroll
            for (int q = 0; q < 4; q++) acc[i][j][q] = 0.f;

    const int NC = K >> 5;

    auto load_chunk = [&](int ci, int st) {
        const int k0 = ci << 5;
        const uint32_t s0 = sb + (uint32_t)st * STAGE;
#pragma unroll
        for (int i = 0; i < AIT; i++) {
            int r = r_ld + i * RPT;
            uint32_t d = (uint32_t)(r * 64 + ((c_ld ^ (r & 3)) << 4));
            long go = (long)r * K + k0 + c_ld * 8;
            cpasync16(s0 + d,       Ah + go);
            cpasync16(s0 + OAL + d, Al + go);
        }
#pragma unroll
        for (int i = 0; i < BIT; i++) {
            int r = r_ld + i * RPT;
            uint32_t d = (uint32_t)(r * 64 + ((c_ld ^ (r & 3)) << 4));
            long go = (long)r * K + k0 + c_ld * 8;
            cpasync16(s0 + OBH + d, Bh + go);
            if (!BSING) cpasync16(s0 + OBL + d, Bl + go);
        }
    };

    const int a_sub = ((lane >> 3) & 1) * 8 + (lane & 7);
    const int a_kc = lane >> 4;
    const int b_sub = ((lane >> 4) & 1) * 8 + (lane & 7);
    const int b_kc = (lane >> 3) & 1;

    load_chunk(0, 0); CP_COMMIT();

    for (int i = 0; i < NC; i++) {
        if (i + 1 < NC) { load_chunk(i + 1, (i + 1) & 1); CP_COMMIT(); CP_WAIT(1); }
        else            { CP_WAIT(0); }
        __syncthreads();
        const uint32_t s0 = sb + ((i & 1) ? (uint32_t)STAGE : 0u);
#pragma unroll
        for (int ks = 0; ks < 2; ks++) {
            uint32_t ah[MI][4], al[MI][4];
#pragma unroll
            for (int mi = 0; mi < MI; mi++) {
                int mrow = wm * WTM + mi * 16 + a_sub;
                int kc = ks * 2 + a_kc;
                uint32_t ad = s0 + mrow * 64 + ((kc ^ (mrow & 3)) << 4);
                ldm_x4(ad, ah[mi]);
                ldm_x4(ad + OAL, al[mi]);
            }
#pragma unroll
            for (int np = 0; np < NB; np++) {
                int nrow = wn * WTN + np * 16 + b_sub;
                int kc = ks * 2 + b_kc;
                uint32_t bd = s0 + OBH + nrow * 64 + ((kc ^ (nrow & 3)) << 4);
                uint32_t bh[4], bl[4];
                ldm_x4(bd, bh);
                if (!BSING) ldm_x4(bd + BN * 64, bl);
#pragma unroll
                for (int mi = 0; mi < MI; mi++)
#pragma unroll
                    for (int j = 0; j < 2; j++) {
                        float* a4 = acc[mi][np * 2 + j];
                        mma16816h(a4, ah[mi], bh + 2 * j);
                        if (!BSING) mma16816h(a4, ah[mi], bl + 2 * j);
                        mma16816h(a4, al[mi], bh + 2 * j);
                    }
            }
        }
        __syncthreads();
    }

    const int er = lane >> 2, ec = (lane & 3) * 2;
    const long mb = wm * WTM + er;
    const int nb = wn * WTN + ec;
#pragma unroll
    for (int mi = 0; mi < MI; mi++)
#pragma unroll
        for (int nj = 0; nj < NJ; nj++) {
            float* p0 = Cp + (mb + mi * 16) * ldc + nb + nj * 8;
            float* p1 = p0 + 8L * ldc;
            *reinterpret_cast<float2*>(p0) = make_float2(acc[mi][nj][0], acc[mi][nj][1]);
            *reinterpret_cast<float2*>(p1) = make_float2(acc[mi][nj][2], acc[mi][nj][3]);
        }
}

// ================= prep: build_dense (6144) + 4 weight transposes (3072) ====
__global__ void prep_kernel(const float* __restrict__ sgm, const int* __restrict__ sb, int Ns,
                            const float* __restrict__ velo, const int* __restrict__ vb, int Nv,
                            const float* __restrict__ Wq, const float* __restrict__ Wk,
                            const float* __restrict__ Wv2, const float* __restrict__ Wv1) {
    __shared__ float t[32][33];
    int bid = blockIdx.x;
    if (bid < 6144) { build_slot(bid, sgm, sb, Ns, velo, vb, Nv); return; }
    bid -= 6144;
    if (bid < 1024) {
        tsp_body1(t, Wq, g_hf + BO_WQV2H, 1024, 1024, bid & 31, bid >> 5);
    } else if (bid < 2048) {
        bid -= 1024;
        tsp_body1(t, Wk, g_hf + BO_WKV1H, 1024, 1024, bid & 31, bid >> 5);
    } else if (bid < 2560) {
        bid -= 2048;
        tsp_body1(t, Wv2, g_hf + BO_WQV2H + 1048576L, 1024, 512, bid & 15, bid >> 4);
    } else {
        bid -= 2560;
        tsp_body1(t, Wv1, g_hf + BO_WKV1H + 1048576L, 1024, 512, bid & 15, bid >> 4);
    }
}

// merged big GEMM: qv2 (blockIdx.y<16) + kv1 (y>=16); B single fp16 (2-term)
__global__ __launch_bounds__(256, 2)
void mma_gemm_big(float* __restrict__ c1, float* __restrict__ c2) {
    extern __shared__ char smem[];
    const uint32_t sb = smem_u32(smem);
    const int K = DD, ldc = 1536;
    const long n0 = (long)blockIdx.x * 128;
    const __half *Ah, *Al, *Bh;
    float* Cp;
    if (blockIdx.y < 16) {
        long m0 = (long)blockIdx.y * 128;
        Ah = g_hf + BO_SGMH + m0 * K;  Al = g_hf + BO_SGML + m0 * K;
        Bh = g_hf + BO_WQV2H + n0 * K;
        Cp = c1 + m0 * ldc + n0;
    } else {
        long m0 = (long)(blockIdx.y - 16) * 128;
        Ah = g_hf + BO_VELOH + m0 * K; Al = g_hf + BO_VELOL + m0 * K;
        Bh = g_hf + BO_WKV1H + n0 * K;
        Cp = c2 + m0 * ldc + n0;
    }
    gemm_body<128, 128, 4, 2, true>(Ah, Al, Bh, Bh, Cp, K, ldc, sb);
}

// ================= MEGA1: scores GEMM + v1T transpose + fc3a v2-half ========
__global__ __launch_bounds__(256)
void mega1_kernel(const float* __restrict__ W3a) {
    extern __shared__ char dsm[];
    int bid = blockIdx.x;
    if (bid < 128) {
        const uint32_t sb = smem_u32(dsm);
        int x = bid & 3, y = (bid >> 2) & 1, z = bid >> 3;
        long m0 = (long)y * 64, n0 = (long)x * 64;
        gemm_body<64, 64, 2, 4>(
            g_hf + BO_QH + (long)z * SS * DD + m0 * DD,
            g_hf + BO_QL + (long)z * SS * DD + m0 * DD,
            g_hf + BO_KH + (long)z * TT * DD + n0 * DD,
            g_hf + BO_KL + (long)z * TT * DD + n0 * DD,
            g_buf + OFF_ATTNF + (long)z * SS * TT + m0 * TT + n0, DD, TT, sb);
    } else if (bid < 2176) {
        int b2 = bid - 128;
        int bx = b2 & 15, by = (b2 >> 4) & 7, bz = b2 >> 7;
        tsp_body(reinterpret_cast<float(*)[33]>(dsm),
                 g_buf + OFF_V1F + (long)bz * TT * 512,
                 g_hf + BO_V1TH + (long)bz * 512 * TT,
                 g_hf + BO_V1TL + (long)bz * 512 * TT,
                 TT, 512, bx, by);
    } else {
        int b3 = bid - 2176;
        fc3a_half_body(reinterpret_cast<float4(*)[5]>(dsm), W3a, b3 & 3, b3 >> 2, 0);
    }
}

// ctx GEMM (batched 64x64, 8 warps, 3-term)
__global__ __launch_bounds__(256, 2)
void ctx_gemm_kernel(float* __restrict__ C) {
    extern __shared__ char smem[];
    const uint32_t sb = smem_u32(smem);
    const int z = blockIdx.z;
    const long m0 = (long)blockIdx.y * 64, n0 = (long)blockIdx.x * 64;
    gemm_body<64, 64, 2, 4>(
        g_hf + BO_ATH + (long)z * SS * TT + m0 * TT,
        g_hf + BO_ATL + (long)z * SS * TT + m0 * TT,
        g_hf + BO_V1TH + (long)z * 512 * TT + n0 * TT,
        g_hf + BO_V1TL + (long)z * 512 * TT + n0 * TT,
        C + (long)z * FIN + m0 * DD + n0, TT, DD, sb);
}

// fc3a ctx-half (1-col, LDS.128): grid (4, 128)
__global__ __launch_bounds__(256)
void fc3a_ctx_kernel(const float* __restrict__ W3a) {
    __shared__ float4 xs[512][5];
    fc3a_half_body(xs, W3a, blockIdx.x, blockIdx.y, 1);
}

// ================= merged dual LayerNorm+ReLU (vectorized) ==================
__global__ void dual_ln2_kernel(const float* __restrict__ in1, const float* __restrict__ in2,
                                const float* __restrict__ gq, const float* __restrict__ bq,
                                const float* __restrict__ gv2, const float* __restrict__ bv2,
                                const float* __restrict__ gk, const float* __restrict__ bk,
                                const float* __restrict__ gv1, const float* __restrict__ bv1,
                                float* __restrict__ dX, float* __restrict__ dV1F) {
    int row = blockIdx.x, t = threadIdx.x;
    int lane = t & 31, wid = t >> 5;
    const float* ip;
    const float *g1, *b1, *g2, *b2;
    __half *oh, *ol;
    float* out2;
    if (row < 2048) {
        ip = in1 + (long)row * 1536;
        g1 = gq; b1 = bq; g2 = gv2; b2 = bv2;
        oh = g_hf + BO_QH + (long)row * 1024;
        ol = g_hf + BO_QL + (long)row * 1024;
        out2 = dX + (long)(row >> 7) * FIN + (long)(row & 127) * 1024;
    } else {
        int r2 = row - 2048;
        ip = in2 + (long)r2 * 1536;
        g1 = gk; b1 = bk; g2 = gv1; b2 = bv1;
        oh = g_hf + BO_KH + (long)r2 * 1024;
        ol = g_hf + BO_KL + (long)r2 * 1024;
        out2 = dV1F + (long)r2 * 512;
    }
    __shared__ float ws[8], wq[8];

    float4 va = *reinterpret_cast<const float4*>(ip + 4 * t);
    float s = va.x + va.y + va.z + va.w;
    float ss = va.x * va.x + va.y * va.y + va.z * va.z + va.w * va.w;
#pragma unroll
    for (int o = 16; o > 0; o >>= 1) {
        s  += __shfl_down_sync(0xffffffffu, s, o);
        ss += __shfl_down_sync(0xffffffffu, ss, o);
    }
    if (lane == 0) { ws[wid] = s; wq[wid] = ss; }
    __syncthreads();
    float st = 0.f, sq = 0.f;
#pragma unroll
    for (int i = 0; i < 8; i++) { st += ws[i]; sq += wq[i]; }
    float mean = st * (1.f / 1024.f);
    float var = sq * (1.f / 1024.f) - mean * mean;
    float r = rsqrtf(var + LN_EPS);
    {
        float4 gg = *reinterpret_cast<const float4*>(g1 + 4 * t);
        float4 bb = *reinterpret_cast<const float4*>(b1 + 4 * t);
        float v0 = fmaxf((va.x - mean) * r * gg.x + bb.x, 0.f);
        float v1 = fmaxf((va.y - mean) * r * gg.y + bb.y, 0.f);
        float v2 = fmaxf((va.z - mean) * r * gg.z + bb.z, 0.f);
        float v3 = fmaxf((va.w - mean) * r * gg.w + bb.w, 0.f);
        uint2 h, l;
        split2h(v0, v1, h.x, l.x);
        split2h(v2, v3, h.y, l.y);
        *reinterpret_cast<uint2*>(oh + 4 * t) = h;
        *reinterpret_cast<uint2*>(ol + 4 * t) = l;
    }

    float2 vb = *reinterpret_cast<const float2*>(ip + 1024 + 2 * t);
    s = vb.x + vb.y;
    ss = vb.x * vb.x + vb.y * vb.y;
#pragma unroll
    for (int o = 16; o > 0; o >>= 1) {
        s  += __shfl_down_sync(0xffffffffu, s, o);
        ss += __shfl_down_sync(0xffffffffu, ss, o);
    }
    __syncthreads();
    if (lane == 0) { ws[wid] = s; wq[wid] = ss; }
    __syncthreads();
    st = 0.f; sq = 0.f;
#pragma unroll
    for (int i = 0; i < 8; i++) { st += ws[i]; sq += wq[i]; }
    mean = st * (1.f / 512.f);
    var = sq * (1.f / 512.f) - mean * mean;
    r = rsqrtf(var + LN_EPS);
    {
        float2 gg = *reinterpret_cast<const float2*>(g2 + 2 * t);
        float2 bb = *reinterpret_cast<const float2*>(b2 + 2 * t);
        float2 o2;
        o2.x = fmaxf((vb.x - mean) * r * gg.x + bb.x, 0.f);
        o2.y = fmaxf((vb.y - mean) * r * gg.y + bb.y, 0.f);
        *reinterpret_cast<float2*>(out2 + 2 * t) = o2;
    }
}

// ================= plain LN+ReLU (fp32 out) =================
__global__ void ln_relu_kernel(const float* __restrict__ in,
                               const float* __restrict__ gamma,
                               const float* __restrict__ beta,
                               float* __restrict__ outp, int C) {
    int row = blockIdx.x;
    int t = threadIdx.x;
    const float* ip = in + (long)row * C;
    float s = 0.f, ss = 0.f;
    for (int c = t; c < C; c += 256) { float v = ip[c]; s += v; ss += v * v; }
    __shared__ float rs[256], rq[256];
    rs[t] = s; rq[t] = ss;
    __syncthreads();
    for (int o = 128; o > 0; o >>= 1) {
        if (t < o) { rs[t] += rs[t + o]; rq[t] += rq[t + o]; }
        __syncthreads();
    }
    float mean = rs[0] / C;
    float var = rq[0] / C - mean * mean;
    float r = rsqrtf(var + LN_EPS);
    float* op = outp + (long)row * C;
    for (int c = t; c < C; c += 256) {
        float v = (ip[c] - mean) * r * gamma[c] + beta[c];
        op[c] = fmaxf(v, 0.f);
    }
}

// ================= softmax (256 wide) -> packed fp16 hi/lo ================
__global__ void softmax_bf_kernel(const float* __restrict__ sc) {
    int row = blockIdx.x;
    int t = threadIdx.x;
    float v = sc[(long)row * 256 + t];
    __shared__ float red[256];
    red[t] = v;
    __syncthreads();
    for (int o = 128; o > 0; o >>= 1) { if (t < o) red[t] = fmaxf(red[t], red[t + o]); __syncthreads(); }
    float mx = red[0];
    __syncthreads();
    float e = __expf(v - mx);
    red[t] = e;
    __syncthreads();
    for (int o = 128; o > 0; o >>= 1) { if (t < o) red[t] += red[t + o]; __syncthreads(); }
    float p = e / red[0];
    float pn = __shfl_down_sync(0xffffffffu, p, 1);
    if ((t & 1) == 0) {
        unsigned h, l;
        split2h(p, pn, h, l);
        *reinterpret_cast<unsigned*>(g_hf + BO_ATH + (long)row * 256 + t) = h;
        *reinterpret_cast<unsigned*>(g_hf + BO_ATL + (long)row * 256 + t) = l;
    }
}

// fused reduce(256 chunks) + LayerNorm + ReLU -> x1; grid 16, block 1024
__global__ __launch_bounds__(1024)
void fc3a_reduce_ln_kernel(const float* __restrict__ part,
                           const float* __restrict__ gamma, const float* __restrict__ beta,
                           float* __restrict__ x1) {
    int b = blockIdx.x, n = threadIdx.x;
    float s = 0.f;
#pragma unroll 4
    for (int c = 0; c < 256; c++) s += part[((long)c * BB + b) * DD + n];
    __shared__ float rs[1024], rq[1024];
    rs[n] = s; rq[n] = s * s;
    __syncthreads();
    for (int o = 512; o > 0; o >>= 1) {
        if (n < o) { rs[n] += rs[n + o]; rq[n] += rq[n + o]; }
        __syncthreads();
    }
    float mean = rs[0] * (1.f / 1024.f);
    float var = rq[0] * (1.f / 1024.f) - mean * mean;
    float r = rsqrtf(var + LN_EPS);
    float v = (s - mean) * r * gamma[n] + beta[n];
    x1[(long)b * DD + n] = fmaxf(v, 0.f);
}

// ================= fc3b: [16,1024] @ [1024,1024] =================
__global__ void small_gemm_kernel(const float* __restrict__ A, const float* __restrict__ W,
                                  float* __restrict__ C, int K, int N) {
    int n = blockIdx.x * 256 + threadIdx.x;
    int b = blockIdx.y;
    float acc = 0.f;
#pragma unroll 4
    for (int k = 0; k < K; k++) acc += A[(long)b * K + k] * W[(long)k * N + n];
    C[(long)b * N + n] = acc;
}

// ================= heads =================
__global__ void heads_kernel(const float* __restrict__ x2,
                             const float* __restrict__ Wr, const float* __restrict__ br,
                             const float* __restrict__ Wt, const float* __restrict__ bt,
                             float* __restrict__ out) {
    int b = blockIdx.x;
    int w = threadIdx.x >> 5, lane = threadIdx.x & 31;
    __shared__ float vals[7];
    if (w < 7) {
        const float* Wp = (w < 4) ? Wr : Wt;
        int ncol = (w < 4) ? 4 : 3;
        int j = (w < 4) ? w : (w - 4);
        float acc = 0.f;
        for (int k = lane; k < DD; k += 32) acc += x2[(long)b * DD + k] * Wp[(long)k * ncol + j];
        for (int o = 16; o > 0; o >>= 1) acc += __shfl_down_sync(0xffffffffu, acc, o);
        if (lane == 0) vals[w] = acc + ((w < 4) ? br[j] : bt[j]);
    }
    __syncthreads();
    if (threadIdx.x == 0) {
        float nn = sqrtf(vals[0]*vals[0] + vals[1]*vals[1] + vals[2]*vals[2] + vals[3]*vals[3]);
        nn = fmaxf(nn, 1e-12f);
        for (int j = 0; j < 4; j++) out[b * 4 + j] = vals[j] / nn;
        for (int j = 0; j < 3; j++) out[64 + b * 3 + j] = vals[4 + j];
    }
}

// ================= host driver =================
extern "C" void kernel_launch(void* const* d_in, const int* in_sizes, int n_in,
                              void* d_out, int out_size) {
    const float* sgm_feats = nullptr; const float* velo_feats = nullptr;
    const int* sbidx = nullptr; const int* vbidx = nullptr;
    int N_sgm = 0, N_velo = 0;
    const float* w[22]; int wi = 0;
    for (int i = 0; i < n_in; i++) {
        int s = in_sizes[i];
        if (s == 3000 * 1024)      { sgm_feats = (const float*)d_in[i]; }
        else if (s == 6000 * 1024) { velo_feats = (const float*)d_in[i]; }
        else if (s == 3000)        { sbidx = (const int*)d_in[i]; N_sgm = s; }
        else if (s == 6000)        { vbidx = (const int*)d_in[i]; N_velo = s; }
        else if (wi < 22)          { w[wi++] = (const float*)d_in[i]; }
    }
    const float *gq = w[1], *bq = w[2];
    const float *Wq = w[0], *Wk = w[3], *gk = w[4], *bk = w[5];
    const float *Wv1 = w[6], *gv1 = w[7], *bv1 = w[8];
    const float *Wv2 = w[9], *gv2 = w[10], *bv2 = w[11];
    const float *W3a = w[12], *g3a = w[13], *b3a = w[14];
    const float *W3b = w[15], *g3b = w[16], *b3b = w[17];
    const float *Wr = w[18], *brr = w[19], *Wt = w[20], *btt = w[21];

    float* fb = nullptr;
    cudaGetSymbolAddress((void**)&fb, g_buf);

    float* dTMP  = fb + OFF_TMP;
    float* dTMP2 = fb + OFF_TMP2;
    float* dV1F  = fb + OFF_V1F;
    float* dX    = fb + OFF_X;
    float* dATT  = fb + OFF_ATTNF;
    float* dPART = fb + OFF_PART;
    float* dX1   = fb + OFF_X1;
    float* dX2   = fb + OFF_X2;
    float* out   = (float*)d_out;

    constexpr int SMEM_A = 2 * (2 * 128 + 128) * 64;   // 49152 (B single)
    constexpr int SMEM_M = 40960;
    cudaFuncSetAttribute(mma_gemm_big, cudaFuncAttributeMaxDynamicSharedMemorySize, SMEM_A);

    // 1. prep: dense build + weight transposes (single fp16)
    prep_kernel<<<6144 + 3072, 256>>>(sgm_feats, sbidx, N_sgm, velo_feats, vbidx, N_velo,
                                      Wq, Wk, Wv2, Wv1);

    // 2. merged big GEMM: [q|v2] + [k|v1]  (A hi/lo, B single: 2-term)
    mma_gemm_big<<<dim3(12, 48), 256, SMEM_A>>>(dTMP, dTMP2);

    // 3. merged dual-LN
    dual_ln2_kernel<<<2048 + 4096, 256>>>(dTMP, dTMP2, gq, bq, gv2, bv2,
                                          gk, bk, gv1, bv1, dX, dV1F);

    // 4. MEGA1: scores + v1T + fc3a v2-half (overlapped)
    mega1_kernel<<<128 + 2048 + 512, 256, SMEM_M>>>(W3a);

    // 5. softmax -> packed fp16 hi/lo
    softmax_bf_kernel<<<BB * SS, 256>>>(dATT);

    // 6. ctx = attn @ v1 -> X[:, s*1024 + 512..1023]
    ctx_gemm_kernel<<<dim3(8, 2, BB), 256, 32768>>>(dX + 512);

    // 7. fc3a ctx-half (LDS.128)
    fc3a_ctx_kernel<<<dim3(4, 128), 256>>>(W3a);

    // 8. fused reduce + LN -> x1
    fc3a_reduce_ln_kernel<<<BB, 1024>>>(dPART, g3a, b3a, dX1);

    // 9. fc3b + LN -> x2
    small_gemm_kernel<<<dim3(DD / 256, BB), 256>>>(dX1, W3b, dTMP, DD, DD);
    ln_relu_kernel<<<BB, 256>>>(dTMP, g3b, b3b, dX2, DD);

    // 10. heads
    heads_kernel<<<BB, 256>>>(dX2, Wr, brr, Wt, btt, out);
    (void)out_size;
}

// round 17
// speedup vs baseline: 1.2263x; 1.1338x over previous
#include <cuda_runtime.h>
#include <cuda_fp16.h>
#include <math.h>
#include <stdint.h>

// ---------------- problem constants ----------------
#define BB   16
#define SS   128
#define TT   256
#define DD   1024
#define FIN  (DD * SS)          // 131072
#define LN_EPS 1e-5f

// ---------------- fp32 scratch (floats) ----------------
#define OFF_TMP   0L             // 3145728 (2048 x 1536)  qv2 out
#define OFF_TMP2  3145728L       // 6291456 (4096 x 1536)  kv1 out
#define OFF_V1F   9437184L       // 2097152 (16*256*512)
#define OFF_X     11534336L      // 2097152 (16*131072)
#define OFF_ATTNF 13631488L      // 524288  (16*128*256)
#define OFF_PART  14155776L      // 4194304 (256*16*1024)
#define OFF_X1    18350080L      // 16384
#define OFF_X2    18366464L      // 16384
#define FBUF_TOTAL 18382848L
__device__ __align__(128) float g_buf[FBUF_TOTAL];

// ---------------- fp16 scratch (elements) ----------------
#define BO_SGMH   0L             // 2097152
#define BO_SGML   2097152L
#define BO_VELOH  4194304L       // 4194304
#define BO_VELOL  8388608L
#define BO_QH     12582912L      // 2097152
#define BO_QL     14680064L
#define BO_KH     16777216L      // 4194304
#define BO_KL     20971520L
#define BO_WQV2H  25165824L      // 1572864 ([1536][1024], single fp16)
#define BO_WKV1H  28311552L      // single fp16
#define BO_V1TH   31457280L      // 2097152 ([16][512][256])
#define BO_V1TL   33554432L
#define BO_ATH    35651584L      // 524288
#define BO_ATL    36175872L
#define BBUF_TOTAL 36700160L
__device__ __align__(128) __half g_hf[BBUF_TOTAL];

// ================= PTX helpers (baseline ISA, plain sm_103) =======
__device__ __forceinline__ uint32_t smem_u32(const void* p) {
    uint32_t a;
    asm("{ .reg .u64 t; cvta.to.shared.u64 t, %1; cvt.u32.u64 %0, t; }" : "=r"(a) : "l"(p));
    return a;
}
__device__ __forceinline__ void cpasync16(uint32_t dst, const void* src) {
    asm volatile("cp.async.cg.shared.global [%0], [%1], 16;" :: "r"(dst), "l"(src));
}
#define CP_COMMIT() asm volatile("cp.async.commit_group;" ::: "memory")
#define CP_WAIT(n)  asm volatile("cp.async.wait_group %0;" :: "n"(n) : "memory")

__device__ __forceinline__ void ldm_x4(uint32_t addr, uint32_t* r) {
    asm volatile("ldmatrix.sync.aligned.m8n8.x4.shared.b16 {%0,%1,%2,%3}, [%4];"
                 : "=r"(r[0]), "=r"(r[1]), "=r"(r[2]), "=r"(r[3]) : "r"(addr));
}
__device__ __forceinline__ void mma16816h(float* d, const uint32_t* a, const uint32_t* b) {
    asm volatile("mma.sync.aligned.m16n8k16.row.col.f32.f16.f16.f32 "
                 "{%0,%1,%2,%3}, {%4,%5,%6,%7}, {%8,%9}, {%0,%1,%2,%3};"
                 : "+f"(d[0]), "+f"(d[1]), "+f"(d[2]), "+f"(d[3])
                 : "r"(a[0]), "r"(a[1]), "r"(a[2]), "r"(a[3]), "r"(b[0]), "r"(b[1]));
}

// ---------------- fp16 split helpers ----------------
__device__ __forceinline__ void split2h(float a, float b, unsigned& h, unsigned& l) {
    __half2 hh = __floats2half2_rn(a, b);
    float ra = a - __half2float(__low2half(hh));
    float rb = b - __half2float(__high2half(hh));
    __half2 ll = __floats2half2_rn(ra, rb);
    h = *reinterpret_cast<unsigned*>(&hh);
    l = *reinterpret_cast<unsigned*>(&ll);
}
__device__ __forceinline__ unsigned pack2h(float a, float b) {
    __half2 hh = __floats2half2_rn(a, b);
    return *reinterpret_cast<unsigned*>(&hh);
}

// ================= dense-build body (gather; zero-fill missing) =============
__device__ __forceinline__ void build_slot(int slot, const float* __restrict__ sgm,
                                           const int* __restrict__ sb, int Ns,
                                           const float* __restrict__ velo,
                                           const int* __restrict__ vb, int Nv) {
    const float* feats; const int* bidx; int N, local; long base, ldelta;
    if (slot < BB * SS) { feats = sgm; bidx = sb; N = Ns; local = SS; base = BO_SGMH; ldelta = BO_SGML - BO_SGMH; }
    else { slot -= BB * SS; feats = velo; bidx = vb; N = Nv; local = TT; base = BO_VELOH; ldelta = BO_VELOL - BO_VELOH; }
    int b = slot / local, r = slot % local;
    __shared__ int s_src;
    if (threadIdx.x == 0) {
        int lo = 0, hi = N;
        while (lo < hi) { int mid = (lo + hi) >> 1; if (bidx[mid] < b) lo = mid + 1; else hi = mid; }
        int src = lo + r;
        s_src = (src < N && bidx[src] == b) ? src : -1;
    }
    __syncthreads();
    int src = s_src;
    __half* dh = g_hf + base + (long)slot * DD;
    __half* dl = dh + ldelta;
    int c = threadIdx.x * 4;
    uint2 h = make_uint2(0, 0), l = make_uint2(0, 0);
    if (src >= 0) {
        const float4 v = *reinterpret_cast<const float4*>(feats + (long)src * DD + c);
        split2h(v.x, v.y, h.x, l.x);
        split2h(v.z, v.w, h.y, l.y);
    }
    *reinterpret_cast<uint2*>(dh + c) = h;
    *reinterpret_cast<uint2*>(dl + c) = l;
}

// ================= transpose bodies =========================================
__device__ __forceinline__ void tsp_body(float (*t)[33], const float* __restrict__ in,
                                         __half* __restrict__ oh, __half* __restrict__ ol,
                                         int R, int C, int bx, int by) {
    int r0 = by * 32, c0 = bx * 32;
    int tx = threadIdx.x & 31, ty = threadIdx.x >> 5;
#pragma unroll
    for (int i = 0; i < 32; i += 8)
        t[ty + i][tx] = in[(long)(r0 + ty + i) * C + c0 + tx];
    __syncthreads();
#pragma unroll
    for (int i = 0; i < 32; i += 8) {
        float v = t[tx][ty + i];
        __half h = __float2half_rn(v);
        __half l = __float2half_rn(v - __half2float(h));
        long o = (long)(c0 + ty + i) * R + r0 + tx;
        oh[o] = h; ol[o] = l;
    }
}
__device__ __forceinline__ void tsp_body1(float (*t)[33], const float* __restrict__ in,
                                          __half* __restrict__ oh,
                                          int R, int C, int bx, int by) {
    int r0 = by * 32, c0 = bx * 32;
    int tx = threadIdx.x & 31, ty = threadIdx.x >> 5;
#pragma unroll
    for (int i = 0; i < 32; i += 8)
        t[ty + i][tx] = in[(long)(r0 + ty + i) * C + c0 + tx];
    __syncthreads();
#pragma unroll
    for (int i = 0; i < 32; i += 8) {
        float v = t[tx][ty + i];
        oh[(long)(c0 + ty + i) * R + r0 + tx] = __float2half_rn(v);
    }
}

// ================= fc3a half body: fp16 MMA (M=16), W cvt fp32->fp16 ========
// xs: 32KB smem: xh 16 kchunks x [16 rows x 64B] @0, xl @16384.
// Block covers n-range [nchunk*256, +256), k-range [f0, f0+512), all 16 b.
// Warp w: n = nchunk*256 + w*32 (4 n8 tiles). acc via mma.m16n8k16.f16.
__device__ __forceinline__ void fc3a_mma_body(__half* xs,
                                              const float* __restrict__ W,
                                              int nchunk, int c, int half) {
    const float* x = g_buf + OFF_X;
    float* part = g_buf + OFF_PART;
    const int f0 = c * 1024 + half * 512;
    const int tid = threadIdx.x, lane = tid & 31, w = tid >> 5;
    const uint32_t sb = smem_u32(xs);
    char* xc = reinterpret_cast<char*>(xs);

    // fill x hi/lo into swizzled smem (gemm-style 64B rows, 16 chunks of 32 k)
#pragma unroll
    for (int it = 0; it < 32; it++) {
        int i = tid + 256 * it;
        int b = i >> 9, f = i & 511;
        float v = x[(long)b * FIN + f0 + f];
        __half h = __float2half_rn(v);
        __half l = __float2half_rn(v - __half2float(h));
        int kc = f >> 5, col = f & 31;
        int off = kc * 1024 + b * 64 + ((((col >> 3) ^ (b & 3))) << 4) + (col & 7) * 2;
        *reinterpret_cast<__half*>(xc + off) = h;
        *reinterpret_cast<__half*>(xc + 16384 + off) = l;
    }
    __syncthreads();

    float acc[4][4];
#pragma unroll
    for (int nt = 0; nt < 4; nt++)
#pragma unroll
        for (int q = 0; q < 4; q++) acc[nt][q] = 0.f;

    const int a_sub = ((lane >> 3) & 1) * 8 + (lane & 7);
    const int a_kc = lane >> 4;
    const int nb = nchunk * 256 + w * 32;
    const int kq = (lane & 3) * 2;   // B k-row base within k16
    const int nn = lane >> 2;        // B n within n8

#pragma unroll 2
    for (int kc = 0; kc < 16; kc++) {
#pragma unroll
        for (int ks = 0; ks < 2; ks++) {
            uint32_t ah[4], al[4];
            uint32_t ad = sb + kc * 1024 + a_sub * 64 + (((ks * 2 + a_kc) ^ (a_sub & 3)) << 4);
            ldm_x4(ad, ah);
            ldm_x4(ad + 16384, al);
            const float* Wk = W + (long)(f0 + kc * 32 + ks * 16 + kq) * DD + nb + nn;
#pragma unroll
            for (int nt = 0; nt < 4; nt++) {
                const float* p = Wk + nt * 8;
                float w0 = p[0];
                float w1 = p[DD];
                float w8 = p[8L * DD];
                float w9 = p[9L * DD];
                uint32_t bb[2];
                bb[0] = pack2h(w0, w1);
                bb[1] = pack2h(w8, w9);
                mma16816h(acc[nt], ah, bb);
                mma16816h(acc[nt], al, bb);
            }
        }
    }
    const int ci = half * 128 + c;
    const int g = lane >> 2, n0 = (lane & 3) * 2;
#pragma unroll
    for (int nt = 0; nt < 4; nt++) {
        long col = nb + nt * 8 + n0;
        *reinterpret_cast<float2*>(&part[((long)ci * BB + g) * DD + col]) =
            make_float2(acc[nt][0], acc[nt][1]);
        *reinterpret_cast<float2*>(&part[((long)ci * BB + g + 8) * DD + col]) =
            make_float2(acc[nt][2], acc[nt][3]);
    }
}

// ================= HMMA GEMM body (fp16; BSING: B single, 2 terms) ==========
template<int BM, int BN, int WM_CNT, int WN_CNT, bool BSING = false>
__device__ __forceinline__ void gemm_body(
    const __half* __restrict__ Ah, const __half* __restrict__ Al,
    const __half* __restrict__ Bh, const __half* __restrict__ Bl,
    float* __restrict__ Cp, int K, int ldc, uint32_t sb) {
    constexpr int T   = 32 * WM_CNT * WN_CNT;
    constexpr int WTM = BM / WM_CNT, WTN = BN / WN_CNT;
    constexpr int MI  = WTM / 16;
    constexpr int NB  = WTN / 16;
    constexpr int NJ  = WTN / 8;
    constexpr int OAL = BM * 64, OBH = 2 * BM * 64, OBL = OBH + BN * 64;
    constexpr int STAGE = (2 * BM + (BSING ? BN : 2 * BN)) * 64;
    constexpr int RPT = T >> 2;
    constexpr int AIT = BM / RPT, BIT = BN / RPT;

    const int tid = threadIdx.x, lane = tid & 31, wid = tid >> 5;
    const int wm = wid % WM_CNT, wn = wid / WM_CNT;
    const int r_ld = tid >> 2, c_ld = tid & 3;

    float acc[MI][NJ][4];
#pragma unroll
    for (int i = 0; i < MI; i++)
#pragma unroll
        for (int j = 0; j < NJ; j++)
#pragma unroll
            for (int q = 0; q < 4; q++) acc[i][j][q] = 0.f;

    const int NC = K >> 5;

    auto load_chunk = [&](int ci, int st) {
        const int k0 = ci << 5;
        const uint32_t s0 = sb + (uint32_t)st * STAGE;
#pragma unroll
        for (int i = 0; i < AIT; i++) {
            int r = r_ld + i * RPT;
            uint32_t d = (uint32_t)(r * 64 + ((c_ld ^ (r & 3)) << 4));
            long go = (long)r * K + k0 + c_ld * 8;
            cpasync16(s0 + d,       Ah + go);
            cpasync16(s0 + OAL + d, Al + go);
        }
#pragma unroll
        for (int i = 0; i < BIT; i++) {
            int r = r_ld + i * RPT;
            uint32_t d = (uint32_t)(r * 64 + ((c_ld ^ (r & 3)) << 4));
            long go = (long)r * K + k0 + c_ld * 8;
            cpasync16(s0 + OBH + d, Bh + go);
            if (!BSING) cpasync16(s0 + OBL + d, Bl + go);
        }
    };

    const int a_sub = ((lane >> 3) & 1) * 8 + (lane & 7);
    const int a_kc = lane >> 4;
    const int b_sub = ((lane >> 4) & 1) * 8 + (lane & 7);
    const int b_kc = (lane >> 3) & 1;

    load_chunk(0, 0); CP_COMMIT();

    for (int i = 0; i < NC; i++) {
        if (i + 1 < NC) { load_chunk(i + 1, (i + 1) & 1); CP_COMMIT(); CP_WAIT(1); }
        else            { CP_WAIT(0); }
        __syncthreads();
        const uint32_t s0 = sb + ((i & 1) ? (uint32_t)STAGE : 0u);
#pragma unroll
        for (int ks = 0; ks < 2; ks++) {
            uint32_t ah[MI][4], al[MI][4];
#pragma unroll
            for (int mi = 0; mi < MI; mi++) {
                int mrow = wm * WTM + mi * 16 + a_sub;
                int kc = ks * 2 + a_kc;
                uint32_t ad = s0 + mrow * 64 + ((kc ^ (mrow & 3)) << 4);
                ldm_x4(ad, ah[mi]);
                ldm_x4(ad + OAL, al[mi]);
            }
#pragma unroll
            for (int np = 0; np < NB; np++) {
                int nrow = wn * WTN + np * 16 + b_sub;
                int kc = ks * 2 + b_kc;
                uint32_t bd = s0 + OBH + nrow * 64 + ((kc ^ (nrow & 3)) << 4);
                uint32_t bh[4], bl[4];
                ldm_x4(bd, bh);
                if (!BSING) ldm_x4(bd + BN * 64, bl);
#pragma unroll
                for (int mi = 0; mi < MI; mi++)
#pragma unroll
                    for (int j = 0; j < 2; j++) {
                        float* a4 = acc[mi][np * 2 + j];
                        mma16816h(a4, ah[mi], bh + 2 * j);
                        if (!BSING) mma16816h(a4, ah[mi], bl + 2 * j);
                        mma16816h(a4, al[mi], bh + 2 * j);
                    }
            }
        }
        __syncthreads();
    }

    const int er = lane >> 2, ec = (lane & 3) * 2;
    const long mb = wm * WTM + er;
    const int nb = wn * WTN + ec;
#pragma unroll
    for (int mi = 0; mi < MI; mi++)
#pragma unroll
        for (int nj = 0; nj < NJ; nj++) {
            float* p0 = Cp + (mb + mi * 16) * ldc + nb + nj * 8;
            float* p1 = p0 + 8L * ldc;
            *reinterpret_cast<float2*>(p0) = make_float2(acc[mi][nj][0], acc[mi][nj][1]);
            *reinterpret_cast<float2*>(p1) = make_float2(acc[mi][nj][2], acc[mi][nj][3]);
        }
}

// ================= prep: build_dense (6144) + 4 weight transposes (3072) ====
__global__ void prep_kernel(const float* __restrict__ sgm, const int* __restrict__ sb, int Ns,
                            const float* __restrict__ velo, const int* __restrict__ vb, int Nv,
                            const float* __restrict__ Wq, const float* __restrict__ Wk,
                            const float* __restrict__ Wv2, const float* __restrict__ Wv1) {
    __shared__ float t[32][33];
    int bid = blockIdx.x;
    if (bid < 6144) { build_slot(bid, sgm, sb, Ns, velo, vb, Nv); return; }
    bid -= 6144;
    if (bid < 1024) {
        tsp_body1(t, Wq, g_hf + BO_WQV2H, 1024, 1024, bid & 31, bid >> 5);
    } else if (bid < 2048) {
        bid -= 1024;
        tsp_body1(t, Wk, g_hf + BO_WKV1H, 1024, 1024, bid & 31, bid >> 5);
    } else if (bid < 2560) {
        bid -= 2048;
        tsp_body1(t, Wv2, g_hf + BO_WQV2H + 1048576L, 1024, 512, bid & 15, bid >> 4);
    } else {
        bid -= 2560;
        tsp_body1(t, Wv1, g_hf + BO_WKV1H + 1048576L, 1024, 512, bid & 15, bid >> 4);
    }
}

// merged big GEMM: qv2 (blockIdx.y<16) + kv1 (y>=16); B single fp16 (2-term)
__global__ __launch_bounds__(256, 2)
void mma_gemm_big(float* __restrict__ c1, float* __restrict__ c2) {
    extern __shared__ char smem[];
    const uint32_t sb = smem_u32(smem);
    const int K = DD, ldc = 1536;
    const long n0 = (long)blockIdx.x * 128;
    const __half *Ah, *Al, *Bh;
    float* Cp;
    if (blockIdx.y < 16) {
        long m0 = (long)blockIdx.y * 128;
        Ah = g_hf + BO_SGMH + m0 * K;  Al = g_hf + BO_SGML + m0 * K;
        Bh = g_hf + BO_WQV2H + n0 * K;
        Cp = c1 + m0 * ldc + n0;
    } else {
        long m0 = (long)(blockIdx.y - 16) * 128;
        Ah = g_hf + BO_VELOH + m0 * K; Al = g_hf + BO_VELOL + m0 * K;
        Bh = g_hf + BO_WKV1H + n0 * K;
        Cp = c2 + m0 * ldc + n0;
    }
    gemm_body<128, 128, 4, 2, true>(Ah, Al, Bh, Bh, Cp, K, ldc, sb);
}

// ================= MEGA1: scores GEMM + v1T transpose + fc3a v2-half ========
// blocks [0,128): scores 64x64 tiles (8 warps); [128,2176): v1T;
// [2176,2688): fc3a v2-half (mma; nchunk = b&3, c = b>>2)
__global__ __launch_bounds__(256)
void mega1_kernel(const float* __restrict__ W3a) {
    extern __shared__ char dsm[];
    int bid = blockIdx.x;
    if (bid < 128) {
        const uint32_t sb = smem_u32(dsm);
        int x = bid & 3, y = (bid >> 2) & 1, z = bid >> 3;
        long m0 = (long)y * 64, n0 = (long)x * 64;
        gemm_body<64, 64, 2, 4>(
            g_hf + BO_QH + (long)z * SS * DD + m0 * DD,
            g_hf + BO_QL + (long)z * SS * DD + m0 * DD,
            g_hf + BO_KH + (long)z * TT * DD + n0 * DD,
            g_hf + BO_KL + (long)z * TT * DD + n0 * DD,
            g_buf + OFF_ATTNF + (long)z * SS * TT + m0 * TT + n0, DD, TT, sb);
    } else if (bid < 2176) {
        int b2 = bid - 128;
        int bx = b2 & 15, by = (b2 >> 4) & 7, bz = b2 >> 7;
        tsp_body(reinterpret_cast<float(*)[33]>(dsm),
                 g_buf + OFF_V1F + (long)bz * TT * 512,
                 g_hf + BO_V1TH + (long)bz * 512 * TT,
                 g_hf + BO_V1TL + (long)bz * 512 * TT,
                 TT, 512, bx, by);
    } else {
        int b3 = bid - 2176;
        fc3a_mma_body(reinterpret_cast<__half*>(dsm), W3a, b3 & 3, b3 >> 2, 0);
    }
}

// ctx GEMM (batched 64x64, 8 warps, 3-term)
__global__ __launch_bounds__(256, 2)
void ctx_gemm_kernel(float* __restrict__ C) {
    extern __shared__ char smem[];
    const uint32_t sb = smem_u32(smem);
    const int z = blockIdx.z;
    const long m0 = (long)blockIdx.y * 64, n0 = (long)blockIdx.x * 64;
    gemm_body<64, 64, 2, 4>(
        g_hf + BO_ATH + (long)z * SS * TT + m0 * TT,
        g_hf + BO_ATL + (long)z * SS * TT + m0 * TT,
        g_hf + BO_V1TH + (long)z * 512 * TT + n0 * TT,
        g_hf + BO_V1TL + (long)z * 512 * TT + n0 * TT,
        C + (long)z * FIN + m0 * DD + n0, TT, DD, sb);
}

// fc3a ctx-half (mma): grid (4, 128)
__global__ __launch_bounds__(256)
void fc3a_ctx_kernel(const float* __restrict__ W3a) {
    __shared__ __half xs[16384];   // 32KB
    fc3a_mma_body(xs, W3a, blockIdx.x, blockIdx.y, 1);
}

// ================= merged dual LayerNorm+ReLU (vectorized) ==================
__global__ void dual_ln2_kernel(const float* __restrict__ in1, const float* __restrict__ in2,
                                const float* __restrict__ gq, const float* __restrict__ bq,
                                const float* __restrict__ gv2, const float* __restrict__ bv2,
                                const float* __restrict__ gk, const float* __restrict__ bk,
                                const float* __restrict__ gv1, const float* __restrict__ bv1,
                                float* __restrict__ dX, float* __restrict__ dV1F) {
    int row = blockIdx.x, t = threadIdx.x;
    int lane = t & 31, wid = t >> 5;
    const float* ip;
    const float *g1, *b1, *g2, *b2;
    __half *oh, *ol;
    float* out2;
    if (row < 2048) {
        ip = in1 + (long)row * 1536;
        g1 = gq; b1 = bq; g2 = gv2; b2 = bv2;
        oh = g_hf + BO_QH + (long)row * 1024;
        ol = g_hf + BO_QL + (long)row * 1024;
        out2 = dX + (long)(row >> 7) * FIN + (long)(row & 127) * 1024;
    } else {
        int r2 = row - 2048;
        ip = in2 + (long)r2 * 1536;
        g1 = gk; b1 = bk; g2 = gv1; b2 = bv1;
        oh = g_hf + BO_KH + (long)r2 * 1024;
        ol = g_hf + BO_KL + (long)r2 * 1024;
        out2 = dV1F + (long)r2 * 512;
    }
    __shared__ float ws[8], wq[8];

    float4 va = *reinterpret_cast<const float4*>(ip + 4 * t);
    float s = va.x + va.y + va.z + va.w;
    float ss = va.x * va.x + va.y * va.y + va.z * va.z + va.w * va.w;
#pragma unroll
    for (int o = 16; o > 0; o >>= 1) {
        s  += __shfl_down_sync(0xffffffffu, s, o);
        ss += __shfl_down_sync(0xffffffffu, ss, o);
    }
    if (lane == 0) { ws[wid] = s; wq[wid] = ss; }
    __syncthreads();
    float st = 0.f, sq = 0.f;
#pragma unroll
    for (int i = 0; i < 8; i++) { st += ws[i]; sq += wq[i]; }
    float mean = st * (1.f / 1024.f);
    float var = sq * (1.f / 1024.f) - mean * mean;
    float r = rsqrtf(var + LN_EPS);
    {
        float4 gg = *reinterpret_cast<const float4*>(g1 + 4 * t);
        float4 bb = *reinterpret_cast<const float4*>(b1 + 4 * t);
        float v0 = fmaxf((va.x - mean) * r * gg.x + bb.x, 0.f);
        float v1 = fmaxf((va.y - mean) * r * gg.y + bb.y, 0.f);
        float v2 = fmaxf((va.z - mean) * r * gg.z + bb.z, 0.f);
        float v3 = fmaxf((va.w - mean) * r * gg.w + bb.w, 0.f);
        uint2 h, l;
        split2h(v0, v1, h.x, l.x);
        split2h(v2, v3, h.y, l.y);
        *reinterpret_cast<uint2*>(oh + 4 * t) = h;
        *reinterpret_cast<uint2*>(ol + 4 * t) = l;
    }

    float2 vb = *reinterpret_cast<const float2*>(ip + 1024 + 2 * t);
    s = vb.x + vb.y;
    ss = vb.x * vb.x + vb.y * vb.y;
#pragma unroll
    for (int o = 16; o > 0; o >>= 1) {
        s  += __shfl_down_sync(0xffffffffu, s, o);
        ss += __shfl_down_sync(0xffffffffu, ss, o);
    }
    __syncthreads();
    if (lane == 0) { ws[wid] = s; wq[wid] = ss; }
    __syncthreads();
    st = 0.f; sq = 0.f;
#pragma unroll
    for (int i = 0; i < 8; i++) { st += ws[i]; sq += wq[i]; }
    mean = st * (1.f / 512.f);
    var = sq * (1.f / 512.f) - mean * mean;
    r = rsqrtf(var + LN_EPS);
    {
        float2 gg = *reinterpret_cast<const float2*>(g2 + 2 * t);
        float2 bb = *reinterpret_cast<const float2*>(b2 + 2 * t);
        float2 o2;
        o2.x = fmaxf((vb.x - mean) * r * gg.x + bb.x, 0.f);
        o2.y = fmaxf((vb.y - mean) * r * gg.y + bb.y, 0.f);
        *reinterpret_cast<float2*>(out2 + 2 * t) = o2;
    }
}

// ================= plain LN+ReLU (fp32 out) =================
__global__ void ln_relu_kernel(const float* __restrict__ in,
                               const float* __restrict__ gamma,
                               const float* __restrict__ beta,
                               float* __restrict__ outp, int C) {
    int row = blockIdx.x;
    int t = threadIdx.x;
    const float* ip = in + (long)row * C;
    float s = 0.f, ss = 0.f;
    for (int c = t; c < C; c += 256) { float v = ip[c]; s += v; ss += v * v; }
    __shared__ float rs[256], rq[256];
    rs[t] = s; rq[t] = ss;
    __syncthreads();
    for (int o = 128; o > 0; o >>= 1) {
        if (t < o) { rs[t] += rs[t + o]; rq[t] += rq[t + o]; }
        __syncthreads();
    }
    float mean = rs[0] / C;
    float var = rq[0] / C - mean * mean;
    float r = rsqrtf(var + LN_EPS);
    float* op = outp + (long)row * C;
    for (int c = t; c < C; c += 256) {
        float v = (ip[c] - mean) * r * gamma[c] + beta[c];
        op[c] = fmaxf(v, 0.f);
    }
}

// ================= softmax (256 wide) -> packed fp16 hi/lo ================
__global__ void softmax_bf_kernel(const float* __restrict__ sc) {
    int row = blockIdx.x;
    int t = threadIdx.x;
    float v = sc[(long)row * 256 + t];
    __shared__ float red[256];
    red[t] = v;
    __syncthreads();
    for (int o = 128; o > 0; o >>= 1) { if (t < o) red[t] = fmaxf(red[t], red[t + o]); __syncthreads(); }
    float mx = red[0];
    __syncthreads();
    float e = __expf(v - mx);
    red[t] = e;
    __syncthreads();
    for (int o = 128; o > 0; o >>= 1) { if (t < o) red[t] += red[t + o]; __syncthreads(); }
    float p = e / red[0];
    float pn = __shfl_down_sync(0xffffffffu, p, 1);
    if ((t & 1) == 0) {
        unsigned h, l;
        split2h(p, pn, h, l);
        *reinterpret_cast<unsigned*>(g_hf + BO_ATH + (long)row * 256 + t) = h;
        *reinterpret_cast<unsigned*>(g_hf + BO_ATL + (long)row * 256 + t) = l;
    }
}

// fused reduce(256 chunks) + LayerNorm + ReLU -> x1; grid 16, block 1024
__global__ __launch_bounds__(1024)
void fc3a_reduce_ln_kernel(const float* __restrict__ part,
                           const float* __restrict__ gamma, const float* __restrict__ beta,
                           float* __restrict__ x1) {
    int b = blockIdx.x, n = threadIdx.x;
    float s = 0.f;
#pragma unroll 4
    for (int c = 0; c < 256; c++) s += part[((long)c * BB + b) * DD + n];
    __shared__ float rs[1024], rq[1024];
    rs[n] = s; rq[n] = s * s;
    __syncthreads();
    for (int o = 512; o > 0; o >>= 1) {
        if (n < o) { rs[n] += rs[n + o]; rq[n] += rq[n + o]; }
        __syncthreads();
    }
    float mean = rs[0] * (1.f / 1024.f);
    float var = rq[0] * (1.f / 1024.f) - mean * mean;
    float r = rsqrtf(var + LN_EPS);
    float v = (s - mean) * r * gamma[n] + beta[n];
    x1[(long)b * DD + n] = fmaxf(v, 0.f);
}

// ================= fc3b: [16,1024] @ [1024,1024] =================
__global__ void small_gemm_kernel(const float* __restrict__ A, const float* __restrict__ W,
                                  float* __restrict__ C, int K, int N) {
    int n = blockIdx.x * 256 + threadIdx.x;
    int b = blockIdx.y;
    float acc = 0.f;
#pragma unroll 4
    for (int k = 0; k < K; k++) acc += A[(long)b * K + k] * W[(long)k * N + n];
    C[(long)b * N + n] = acc;
}

// ================= heads =================
__global__ void heads_kernel(const float* __restrict__ x2,
                             const float* __restrict__ Wr, const float* __restrict__ br,
                             const float* __restrict__ Wt, const float* __restrict__ bt,
                             float* __restrict__ out) {
    int b = blockIdx.x;
    int w = threadIdx.x >> 5, lane = threadIdx.x & 31;
    __shared__ float vals[7];
    if (w < 7) {
        const float* Wp = (w < 4) ? Wr : Wt;
        int ncol = (w < 4) ? 4 : 3;
        int j = (w < 4) ? w : (w - 4);
        float acc = 0.f;
        for (int k = lane; k < DD; k += 32) acc += x2[(long)b * DD + k] * Wp[(long)k * ncol + j];
        for (int o = 16; o > 0; o >>= 1) acc += __shfl_down_sync(0xffffffffu, acc, o);
        if (lane == 0) vals[w] = acc + ((w < 4) ? br[j] : bt[j]);
    }
    __syncthreads();
    if (threadIdx.x == 0) {
        float nn = sqrtf(vals[0]*vals[0] + vals[1]*vals[1] + vals[2]*vals[2] + vals[3]*vals[3]);
        nn = fmaxf(nn, 1e-12f);
        for (int j = 0; j < 4; j++) out[b * 4 + j] = vals[j] / nn;
        for (int j = 0; j < 3; j++) out[64 + b * 3 + j] = vals[4 + j];
    }
}

// ================= host driver =================
extern "C" void kernel_launch(void* const* d_in, const int* in_sizes, int n_in,
                              void* d_out, int out_size) {
    const float* sgm_feats = nullptr; const float* velo_feats = nullptr;
    const int* sbidx = nullptr; const int* vbidx = nullptr;
    int N_sgm = 0, N_velo = 0;
    const float* w[22]; int wi = 0;
    for (int i = 0; i < n_in; i++) {
        int s = in_sizes[i];
        if (s == 3000 * 1024)      { sgm_feats = (const float*)d_in[i]; }
        else if (s == 6000 * 1024) { velo_feats = (const float*)d_in[i]; }
        else if (s == 3000)        { sbidx = (const int*)d_in[i]; N_sgm = s; }
        else if (s == 6000)        { vbidx = (const int*)d_in[i]; N_velo = s; }
        else if (wi < 22)          { w[wi++] = (const float*)d_in[i]; }
    }
    const float *gq = w[1], *bq = w[2];
    const float *Wq = w[0], *Wk = w[3], *gk = w[4], *bk = w[5];
    const float *Wv1 = w[6], *gv1 = w[7], *bv1 = w[8];
    const float *Wv2 = w[9], *gv2 = w[10], *bv2 = w[11];
    const float *W3a = w[12], *g3a = w[13], *b3a = w[14];
    const float *W3b = w[15], *g3b = w[16], *b3b = w[17];
    const float *Wr = w[18], *brr = w[19], *Wt = w[20], *btt = w[21];

    float* fb = nullptr;
    cudaGetSymbolAddress((void**)&fb, g_buf);

    float* dTMP  = fb + OFF_TMP;
    float* dTMP2 = fb + OFF_TMP2;
    float* dV1F  = fb + OFF_V1F;
    float* dX    = fb + OFF_X;
    float* dATT  = fb + OFF_ATTNF;
    float* dPART = fb + OFF_PART;
    float* dX1   = fb + OFF_X1;
    float* dX2   = fb + OFF_X2;
    float* out   = (float*)d_out;

    constexpr int SMEM_A = 2 * (2 * 128 + 128) * 64;   // 49152 (B single)
    constexpr int SMEM_M = 32768;
    cudaFuncSetAttribute(mma_gemm_big, cudaFuncAttributeMaxDynamicSharedMemorySize, SMEM_A);

    // 1. prep: dense build + weight transposes (single fp16)
    prep_kernel<<<6144 + 3072, 256>>>(sgm_feats, sbidx, N_sgm, velo_feats, vbidx, N_velo,
                                      Wq, Wk, Wv2, Wv1);

    // 2. merged big GEMM: [q|v2] + [k|v1]  (A hi/lo, B single: 2-term)
    mma_gemm_big<<<dim3(12, 48), 256, SMEM_A>>>(dTMP, dTMP2);

    // 3. merged dual-LN
    dual_ln2_kernel<<<2048 + 4096, 256>>>(dTMP, dTMP2, gq, bq, gv2, bv2,
                                          gk, bk, gv1, bv1, dX, dV1F);

    // 4. MEGA1: scores + v1T + fc3a v2-half (fp16 MMA, overlapped)
    mega1_kernel<<<128 + 2048 + 512, 256, SMEM_M>>>(W3a);

    // 5. softmax -> packed fp16 hi/lo
    softmax_bf_kernel<<<BB * SS, 256>>>(dATT);

    // 6. ctx = attn @ v1 -> X[:, s*1024 + 512..1023]
    ctx_gemm_kernel<<<dim3(8, 2, BB), 256, 32768>>>(dX + 512);

    // 7. fc3a ctx-half (fp16 MMA)
    fc3a_ctx_kernel<<<dim3(4, 128), 256>>>(W3a);

    // 8. fused reduce + LN -> x1
    fc3a_reduce_ln_kernel<<<BB, 1024>>>(dPART, g3a, b3a, dX1);

    // 9. fc3b + LN -> x2
    small_gemm_kernel<<<dim3(DD / 256, BB), 256>>>(dX1, W3b, dTMP, DD, DD);
    ln_relu_kernel<<<BB, 256>>>(dTMP, g3b, b3b, dX2, DD);

    // 10. heads
    heads_kernel<<<BB, 256>>>(dX2, Wr, brr, Wt, btt, out);
    (void)out_size;
}